// round 1
// baseline (speedup 1.0000x reference)
#include <cuda_runtime.h>
#include <math.h>

#define D_MODEL 1024
#define N_HEADS 16
#define DH      64
#define BATCH   2
#define SEQ     2048
#define M_ROWS  (BATCH*SEQ)   // 4096

// ---------------- scratch (static device globals; no allocations) ----------
__device__ float g_XN [M_ROWS*D_MODEL];   // x_norm / o_norm (reused)
__device__ float g_Q  [M_ROWS*D_MODEL];   // q proj / swiglu (reused)
__device__ float g_K  [M_ROWS*D_MODEL];
__device__ float g_V  [M_ROWS*D_MODEL];
__device__ float g_U  [M_ROWS*D_MODEL];
__device__ float g_AO [M_ROWS*D_MODEL];   // attention out -> ams_out (in place)
__device__ float g_O  [M_ROWS*D_MODEL];   // mffn residual
__device__ float g_X12[M_ROWS*2*D_MODEL];

__device__ __forceinline__ float siluf(float z) {
    return z * (1.0f / (1.0f + __expf(-z)));
}

// ---------------- RMSNorm: one block per row, d=1024, 256 thr x float4 -----
__global__ void __launch_bounds__(256)
rmsnorm_k(const float* __restrict__ X, const float* __restrict__ g,
          float* __restrict__ Y)
{
    int r = blockIdx.x, t = threadIdx.x;
    float4 v = ((const float4*)(X + (size_t)r * D_MODEL))[t];
    float ss = v.x*v.x + v.y*v.y + v.z*v.z + v.w*v.w;
    #pragma unroll
    for (int o = 16; o; o >>= 1) ss += __shfl_xor_sync(0xffffffffu, ss, o);
    __shared__ float ws[8];
    __shared__ float s_inv;
    if ((t & 31) == 0) ws[t >> 5] = ss;
    __syncthreads();
    if (t == 0) {
        float tot = 0.f;
        #pragma unroll
        for (int i = 0; i < 8; i++) tot += ws[i];
        s_inv = rsqrtf(tot * (1.0f / D_MODEL) + 1e-8f);
    }
    __syncthreads();
    float iv = s_inv;
    float4 gv = ((const float4*)g)[t];
    float4 o;
    o.x = v.x * iv * gv.x; o.y = v.y * iv * gv.y;
    o.z = v.z * iv * gv.z; o.w = v.w * iv * gv.w;
    ((float4*)(Y + (size_t)r * D_MODEL))[t] = o;
}

// -------- ams: A = rmsnorm(A, g) * U, in place, one block per row ----------
__global__ void __launch_bounds__(256)
ams_k(float* __restrict__ A, const float* __restrict__ g,
      const float* __restrict__ U)
{
    int r = blockIdx.x, t = threadIdx.x;
    float4 v = ((float4*)(A + (size_t)r * D_MODEL))[t];
    float ss = v.x*v.x + v.y*v.y + v.z*v.z + v.w*v.w;
    #pragma unroll
    for (int o = 16; o; o >>= 1) ss += __shfl_xor_sync(0xffffffffu, ss, o);
    __shared__ float ws[8];
    __shared__ float s_inv;
    if ((t & 31) == 0) ws[t >> 5] = ss;
    __syncthreads();
    if (t == 0) {
        float tot = 0.f;
        #pragma unroll
        for (int i = 0; i < 8; i++) tot += ws[i];
        s_inv = rsqrtf(tot * (1.0f / D_MODEL) + 1e-8f);
    }
    __syncthreads();
    float iv = s_inv;
    float4 gv = ((const float4*)g)[t];
    float4 uv = ((const float4*)(U + (size_t)r * D_MODEL))[t];
    float4 o;
    o.x = v.x * iv * gv.x * uv.x; o.y = v.y * iv * gv.y * uv.y;
    o.z = v.z * iv * gv.z * uv.z; o.w = v.w * iv * gv.w * uv.w;
    ((float4*)(A + (size_t)r * D_MODEL))[t] = o;
}

// -------- swiglu: SG[r,c] = silu(X12[r,c]) * X12[r,c+1024] -----------------
__global__ void __launch_bounds__(256)
swiglu_k(const float* __restrict__ X12, float* __restrict__ SG)
{
    int i4 = blockIdx.x * blockDim.x + threadIdx.x;   // 0 .. 1048575
    int r  = i4 >> 8;
    int c4 = i4 & 255;
    float4 a = ((const float4*)(X12 + (size_t)r * 2048))[c4];
    float4 b = ((const float4*)(X12 + (size_t)r * 2048 + 1024))[c4];
    float4 o;
    o.x = siluf(a.x) * b.x; o.y = siluf(a.y) * b.y;
    o.z = siluf(a.z) * b.z; o.w = siluf(a.w) * b.w;
    ((float4*)(SG + (size_t)r * 1024))[c4] = o;
}

// ---------------- SGEMM: C = A[MxK] @ B[KxN] + bias (+ epi) ----------------
// EPI: 0 = bias only, 1 = silu(acc+bias), 2 = acc+bias+R (residual)
#define BM 128
#define BN 128
#define BK 16
#define AS_STRIDE 132

template<int EPI>
__global__ void __launch_bounds__(256)
sgemm_k(const float* __restrict__ A, const float* __restrict__ B,
        const float* __restrict__ bias, const float* __restrict__ R,
        float* __restrict__ C, int M, int N, int K)
{
    __shared__ float As[BK * AS_STRIDE];   // A transposed: As[k][m]
    __shared__ float Bs[BK * BN];          // Bs[k][n]
    int tid = threadIdx.x;
    int tx = tid & 15, ty = tid >> 4;
    int bm = blockIdx.y * BM, bn = blockIdx.x * BN;
    int aRow = tid >> 2,  aCol = (tid & 3) << 2;
    int bRow = tid >> 5,  bCol = (tid & 31) << 2;

    float acc[8][8];
    #pragma unroll
    for (int i = 0; i < 8; i++)
        #pragma unroll
        for (int j = 0; j < 8; j++) acc[i][j] = 0.f;

    for (int k0 = 0; k0 < K; k0 += BK) {
        #pragma unroll
        for (int i = 0; i < 2; i++) {
            float4 a = *(const float4*)&A[(size_t)(bm + aRow + i*64) * K + k0 + aCol];
            As[(aCol+0)*AS_STRIDE + aRow + i*64] = a.x;
            As[(aCol+1)*AS_STRIDE + aRow + i*64] = a.y;
            As[(aCol+2)*AS_STRIDE + aRow + i*64] = a.z;
            As[(aCol+3)*AS_STRIDE + aRow + i*64] = a.w;
        }
        #pragma unroll
        for (int i = 0; i < 2; i++) {
            *(float4*)&Bs[(bRow + i*8)*BN + bCol] =
                *(const float4*)&B[(size_t)(k0 + bRow + i*8) * N + bn + bCol];
        }
        __syncthreads();
        #pragma unroll
        for (int kk = 0; kk < BK; kk++) {
            float a[8], b[8];
            *(float4*)&a[0] = *(const float4*)&As[kk*AS_STRIDE + ty*8];
            *(float4*)&a[4] = *(const float4*)&As[kk*AS_STRIDE + ty*8 + 4];
            *(float4*)&b[0] = *(const float4*)&Bs[kk*BN + tx*8];
            *(float4*)&b[4] = *(const float4*)&Bs[kk*BN + tx*8 + 4];
            #pragma unroll
            for (int i = 0; i < 8; i++)
                #pragma unroll
                for (int j = 0; j < 8; j++)
                    acc[i][j] = fmaf(a[i], b[j], acc[i][j]);
        }
        __syncthreads();
    }

    float bvv[8];
    #pragma unroll
    for (int j = 0; j < 8; j++) bvv[j] = bias[bn + tx*8 + j];

    #pragma unroll
    for (int i = 0; i < 8; i++) {
        int row = bm + ty*8 + i;
        size_t off = (size_t)row * N + bn + tx*8;
        float o[8];
        #pragma unroll
        for (int j = 0; j < 8; j++) {
            float v = acc[i][j] + bvv[j];
            if (EPI == 1) v = siluf(v);
            if (EPI == 2) v += R[off + j];
            o[j] = v;
        }
        *(float4*)&C[off]     = make_float4(o[0], o[1], o[2], o[3]);
        *(float4*)&C[off + 4] = make_float4(o[4], o[5], o[6], o[7]);
    }
}

// ---------------- fused SiLU-attention -------------------------------------
// out[b,h,qi,:] = sum_t silu(q.k_t * 0.125 + pb[t,h]) * v_t
// block: 64 q rows x dh=64, loop over 32 key tiles of 64. 256 threads, 4x4 micro.
__global__ void __launch_bounds__(256)
attn_k(const float* __restrict__ Q, const float* __restrict__ K,
       const float* __restrict__ V, const float* __restrict__ PB,
       float* __restrict__ O)
{
    extern __shared__ float sm[];
    float* qT  = sm;              // [c][r]  64 x stride 68
    float* kT  = sm + 4352;       // [c][t]
    float* sS  = sm + 2*4352;     // [i][t]
    float* vS  = sm + 3*4352;     // [t][c]
    float* pbs = sm + 4*4352;     // [64]

    int tid = threadIdx.x;
    int tx = tid & 15, ty = tid >> 4;
    int qt = blockIdx.x, h = blockIdx.y, b = blockIdx.z;
    size_t headOff = (size_t)h * DH;

    // load Q tile transposed (lanes span rows -> conflict-free STS)
    {
        int r  = tid & 63;
        int cb = (tid >> 6) << 4;
        const float* qp = Q + ((size_t)(b*SEQ + qt*64 + r)) * D_MODEL + headOff + cb;
        #pragma unroll
        for (int it = 0; it < 4; it++) {
            float4 a = *(const float4*)(qp + it*4);
            int c = cb + it*4;
            qT[(c+0)*68 + r] = a.x; qT[(c+1)*68 + r] = a.y;
            qT[(c+2)*68 + r] = a.z; qT[(c+3)*68 + r] = a.w;
        }
    }

    float acc[4][4];
    #pragma unroll
    for (int i = 0; i < 4; i++)
        #pragma unroll
        for (int j = 0; j < 4; j++) acc[i][j] = 0.f;

    for (int kt = 0; kt < SEQ/64; kt++) {
        __syncthreads();   // also covers q-load on first iter, prior out-GEMM after
        // K tile transposed
        {
            int r  = tid & 63;
            int cb = (tid >> 6) << 4;
            const float* kp = K + ((size_t)(b*SEQ + kt*64 + r)) * D_MODEL + headOff + cb;
            #pragma unroll
            for (int it = 0; it < 4; it++) {
                float4 a = *(const float4*)(kp + it*4);
                int c = cb + it*4;
                kT[(c+0)*68 + r] = a.x; kT[(c+1)*68 + r] = a.y;
                kT[(c+2)*68 + r] = a.z; kT[(c+3)*68 + r] = a.w;
            }
        }
        // V tile natural
        #pragma unroll
        for (int it = 0; it < 4; it++) {
            int L = tid*4 + it*1024;
            int tr = L >> 6, tc = L & 63;
            float4 a = *(const float4*)(V + ((size_t)(b*SEQ + kt*64 + tr)) * D_MODEL + headOff + tc);
            *(float4*)&vS[tr*68 + tc] = a;
        }
        if (tid < 64) pbs[tid] = PB[(size_t)(kt*64 + tid) * N_HEADS + h];
        __syncthreads();

        // s = q @ k^T
        float s[4][4];
        #pragma unroll
        for (int i = 0; i < 4; i++)
            #pragma unroll
            for (int j = 0; j < 4; j++) s[i][j] = 0.f;
        #pragma unroll 8
        for (int kk = 0; kk < 64; kk++) {
            float4 a4 = *(const float4*)&qT[kk*68 + ty*4];
            float4 b4 = *(const float4*)&kT[kk*68 + tx*4];
            float av[4] = {a4.x, a4.y, a4.z, a4.w};
            float bv[4] = {b4.x, b4.y, b4.z, b4.w};
            #pragma unroll
            for (int i = 0; i < 4; i++)
                #pragma unroll
                for (int j = 0; j < 4; j++)
                    s[i][j] = fmaf(av[i], bv[j], s[i][j]);
        }
        // silu(s*scale + pbias[t]) -> smem
        #pragma unroll
        for (int i = 0; i < 4; i++)
            #pragma unroll
            for (int j = 0; j < 4; j++) {
                float z = s[i][j] * 0.125f + pbs[tx*4 + j];
                sS[(ty*4 + i)*68 + tx*4 + j] = siluf(z);
            }
        __syncthreads();

        // acc += s @ v
        #pragma unroll 8
        for (int t = 0; t < 64; t++) {
            float a0 = sS[(ty*4 + 0)*68 + t];
            float a1 = sS[(ty*4 + 1)*68 + t];
            float a2 = sS[(ty*4 + 2)*68 + t];
            float a3 = sS[(ty*4 + 3)*68 + t];
            float4 b4 = *(const float4*)&vS[t*68 + tx*4];
            float bv[4] = {b4.x, b4.y, b4.z, b4.w};
            #pragma unroll
            for (int j = 0; j < 4; j++) {
                acc[0][j] = fmaf(a0, bv[j], acc[0][j]);
                acc[1][j] = fmaf(a1, bv[j], acc[1][j]);
                acc[2][j] = fmaf(a2, bv[j], acc[2][j]);
                acc[3][j] = fmaf(a3, bv[j], acc[3][j]);
            }
        }
    }

    #pragma unroll
    for (int i = 0; i < 4; i++) {
        size_t off = ((size_t)(b*SEQ + qt*64 + ty*4 + i)) * D_MODEL + headOff + tx*4;
        *(float4*)&O[off] = make_float4(acc[i][0], acc[i][1], acc[i][2], acc[i][3]);
    }
}

// ---------------- launch ----------------------------------------------------
extern "C" void kernel_launch(void* const* d_in, const int* in_sizes, int n_in,
                              void* d_out, int out_size)
{
    const float* x      = (const float*)d_in[0];
    const float* pb     = (const float*)d_in[2];
    const float* wq     = (const float*)d_in[3];
    const float* bq     = (const float*)d_in[4];
    const float* wk     = (const float*)d_in[5];
    const float* bk_    = (const float*)d_in[6];
    const float* wv     = (const float*)d_in[7];
    const float* bv     = (const float*)d_in[8];
    const float* wu     = (const float*)d_in[9];
    const float* bu     = (const float*)d_in[10];
    const float* g_ams  = (const float*)d_in[11];
    const float* w0     = (const float*)d_in[12];
    const float* b0     = (const float*)d_in[13];
    const float* w1     = (const float*)d_in[14];
    const float* b1     = (const float*)d_in[15];
    const float* w2     = (const float*)d_in[16];
    const float* b2     = (const float*)d_in[17];
    const float* g_mffn = (const float*)d_in[18];
    float* out = (float*)d_out;

    float *XN, *Qb, *Kb, *Vb, *Ub, *AO, *Ob, *X12;
    cudaGetSymbolAddress((void**)&XN,  g_XN);
    cudaGetSymbolAddress((void**)&Qb,  g_Q);
    cudaGetSymbolAddress((void**)&Kb,  g_K);
    cudaGetSymbolAddress((void**)&Vb,  g_V);
    cudaGetSymbolAddress((void**)&Ub,  g_U);
    cudaGetSymbolAddress((void**)&AO,  g_AO);
    cudaGetSymbolAddress((void**)&Ob,  g_O);
    cudaGetSymbolAddress((void**)&X12, g_X12);

    cudaFuncSetAttribute(attn_k, cudaFuncAttributeMaxDynamicSharedMemorySize, 69888);

    dim3 gP(D_MODEL/BN, M_ROWS/BM);           // (8, 32)
    dim3 gW1(2*D_MODEL/BN, M_ROWS/BM);        // (16, 32)

    // x_norm = rmsnorm(x, g_ams)
    rmsnorm_k<<<M_ROWS, 256>>>(x, g_ams, XN);
    // q,k,v projections; u = silu(xn@wu+bu)
    sgemm_k<0><<<gP, 256>>>(XN, wq, bq,  nullptr, Qb, M_ROWS, D_MODEL, D_MODEL);
    sgemm_k<0><<<gP, 256>>>(XN, wk, bk_, nullptr, Kb, M_ROWS, D_MODEL, D_MODEL);
    sgemm_k<0><<<gP, 256>>>(XN, wv, bv,  nullptr, Vb, M_ROWS, D_MODEL, D_MODEL);
    sgemm_k<1><<<gP, 256>>>(XN, wu, bu,  nullptr, Ub, M_ROWS, D_MODEL, D_MODEL);
    // fused silu-attention
    attn_k<<<dim3(SEQ/64, N_HEADS, BATCH), 256, 69888>>>(Qb, Kb, Vb, pb, AO);
    // ams_out = rmsnorm(attn_out, g_ams) * u   (in place in AO)
    ams_k<<<M_ROWS, 256>>>(AO, g_ams, Ub);
    // o = ams_out @ w0 + b0 + x
    sgemm_k<2><<<gP, 256>>>(AO, w0, b0, x, Ob, M_ROWS, D_MODEL, D_MODEL);
    // o_norm = rmsnorm(o, g_mffn)
    rmsnorm_k<<<M_ROWS, 256>>>(Ob, g_mffn, XN);
    // x12 = o_norm @ w1 + b1
    sgemm_k<0><<<gW1, 256>>>(XN, w1, b1, nullptr, X12, M_ROWS, 2*D_MODEL, D_MODEL);
    // swiglu = silu(x1) * x2   (into Qb, reused)
    swiglu_k<<<4096, 256>>>(X12, Qb);
    // out = swiglu @ w2 + b2 + o
    sgemm_k<2><<<gP, 256>>>(Qb, w2, b2, Ob, out, M_ROWS, D_MODEL, D_MODEL);
}

// round 3
// speedup vs baseline: 1.3966x; 1.3966x over previous
#include <cuda_runtime.h>
#include <cuda_bf16.h>
#include <cstdint>
#include <math.h>

#define D_MODEL 1024
#define N_HEADS 16
#define DH      64
#define BATCH   2
#define SEQ     2048
#define M_ROWS  (BATCH*SEQ)   // 4096

// ---------------- scratch (static device globals; no allocations) ----------
__device__ float g_Q  [M_ROWS*D_MODEL];
__device__ float g_K  [M_ROWS*D_MODEL];
__device__ float g_V  [M_ROWS*D_MODEL];
__device__ float g_U  [M_ROWS*D_MODEL];
__device__ float g_AO [M_ROWS*D_MODEL];
__device__ float g_O  [M_ROWS*D_MODEL];
__device__ float g_X12[M_ROWS*2*D_MODEL];

// bf16 hi/lo activation buffers
__device__ __nv_bfloat16 g_A1h[M_ROWS*D_MODEL];
__device__ __nv_bfloat16 g_A1l[M_ROWS*D_MODEL];
__device__ __nv_bfloat16 g_A2h[M_ROWS*D_MODEL];
__device__ __nv_bfloat16 g_A2l[M_ROWS*D_MODEL];

// transposed + split weights: [N,K] bf16
__device__ __nv_bfloat16 g_WTh[8*1024*1024];
__device__ __nv_bfloat16 g_WTl[8*1024*1024];

__device__ __forceinline__ float siluf(float z) {
    return z * (1.0f / (1.0f + __expf(-z)));
}

__device__ __forceinline__ uint32_t smem_u32(const void* p) {
    uint32_t a;
    asm("{ .reg .u64 t; cvta.to.shared.u64 t, %1; cvt.u32.u64 %0, t; }" : "=r"(a) : "l"(p));
    return a;
}

__device__ __forceinline__ void ldsm_x4(uint32_t* r, uint32_t a) {
    asm volatile("ldmatrix.sync.aligned.m8n8.x4.shared.b16 {%0,%1,%2,%3}, [%4];"
                 : "=r"(r[0]), "=r"(r[1]), "=r"(r[2]), "=r"(r[3]) : "r"(a));
}

__device__ __forceinline__ void mma16816(float* c, const uint32_t* a, uint32_t b0, uint32_t b1) {
    asm volatile("mma.sync.aligned.m16n8k16.row.col.f32.bf16.bf16.f32 "
                 "{%0,%1,%2,%3}, {%4,%5,%6,%7}, {%8,%9}, {%0,%1,%2,%3};"
                 : "+f"(c[0]), "+f"(c[1]), "+f"(c[2]), "+f"(c[3])
                 : "r"(a[0]), "r"(a[1]), "r"(a[2]), "r"(a[3]), "r"(b0), "r"(b1));
}

__device__ __forceinline__ void cp16(uint32_t dst, const void* src) {
    asm volatile("cp.async.cg.shared.global [%0], [%1], 16;" :: "r"(dst), "l"(src));
}
__device__ __forceinline__ void cp_commit() { asm volatile("cp.async.commit_group;"); }
__device__ __forceinline__ void cp_wait1()  { asm volatile("cp.async.wait_group 1;"); }
__device__ __forceinline__ void cp_wait0()  { asm volatile("cp.async.wait_group 0;"); }

// ============ weight transpose + bf16 split: W[K,N] -> T[N,K] hi/lo ========
__global__ void __launch_bounds__(256)
wtsplit_k(const float* __restrict__ W, __nv_bfloat16* __restrict__ Thi,
          __nv_bfloat16* __restrict__ Tlo, int K, int N)
{
    __shared__ float t[32][33];
    int tx = threadIdx.x, ty = threadIdx.y;           // (32, 8)
    int n0 = blockIdx.x * 32, k0 = blockIdx.y * 32;
    #pragma unroll
    for (int i = 0; i < 4; i++)
        t[ty + i*8][tx] = W[(size_t)(k0 + ty + i*8) * N + n0 + tx];
    __syncthreads();
    #pragma unroll
    for (int i = 0; i < 4; i++) {
        float v = t[tx][ty + i*8];
        __nv_bfloat16 hi = __float2bfloat16(v);
        __nv_bfloat16 lo = __float2bfloat16(v - __bfloat162float(hi));
        size_t off = (size_t)(n0 + ty + i*8) * K + k0 + tx;
        Thi[off] = hi; Tlo[off] = lo;
    }
}

// ---------------- RMSNorm -> bf16 hi/lo -------------------------------------
__global__ void __launch_bounds__(256)
rmsnorm_tc(const float* __restrict__ X, const float* __restrict__ g,
           __nv_bfloat16* __restrict__ Yh, __nv_bfloat16* __restrict__ Yl)
{
    int r = blockIdx.x, t = threadIdx.x;
    float4 v = ((const float4*)(X + (size_t)r * D_MODEL))[t];
    float ss = v.x*v.x + v.y*v.y + v.z*v.z + v.w*v.w;
    #pragma unroll
    for (int o = 16; o; o >>= 1) ss += __shfl_xor_sync(0xffffffffu, ss, o);
    __shared__ float ws[8]; __shared__ float s_inv;
    if ((t & 31) == 0) ws[t >> 5] = ss;
    __syncthreads();
    if (t == 0) {
        float tot = 0.f;
        #pragma unroll
        for (int i = 0; i < 8; i++) tot += ws[i];
        s_inv = rsqrtf(tot * (1.0f / D_MODEL) + 1e-8f);
    }
    __syncthreads();
    float iv = s_inv;
    float4 gv = ((const float4*)g)[t];
    float o[4] = {v.x*iv*gv.x, v.y*iv*gv.y, v.z*iv*gv.z, v.w*iv*gv.w};
    __nv_bfloat16 h[4], l[4];
    #pragma unroll
    for (int i = 0; i < 4; i++) {
        h[i] = __float2bfloat16(o[i]);
        l[i] = __float2bfloat16(o[i] - __bfloat162float(h[i]));
    }
    size_t base = (size_t)r * D_MODEL + t*4;
    *(__nv_bfloat162*)(Yh + base)     = __nv_bfloat162(h[0], h[1]);
    *(__nv_bfloat162*)(Yh + base + 2) = __nv_bfloat162(h[2], h[3]);
    *(__nv_bfloat162*)(Yl + base)     = __nv_bfloat162(l[0], l[1]);
    *(__nv_bfloat162*)(Yl + base + 2) = __nv_bfloat162(l[2], l[3]);
}

// -------- ams: out = rmsnorm(A, g) * U -> bf16 hi/lo ------------------------
__global__ void __launch_bounds__(256)
ams_tc(const float* __restrict__ A, const float* __restrict__ g,
       const float* __restrict__ U,
       __nv_bfloat16* __restrict__ Yh, __nv_bfloat16* __restrict__ Yl)
{
    int r = blockIdx.x, t = threadIdx.x;
    float4 v = ((const float4*)(A + (size_t)r * D_MODEL))[t];
    float ss = v.x*v.x + v.y*v.y + v.z*v.z + v.w*v.w;
    #pragma unroll
    for (int o = 16; o; o >>= 1) ss += __shfl_xor_sync(0xffffffffu, ss, o);
    __shared__ float ws[8]; __shared__ float s_inv;
    if ((t & 31) == 0) ws[t >> 5] = ss;
    __syncthreads();
    if (t == 0) {
        float tot = 0.f;
        #pragma unroll
        for (int i = 0; i < 8; i++) tot += ws[i];
        s_inv = rsqrtf(tot * (1.0f / D_MODEL) + 1e-8f);
    }
    __syncthreads();
    float iv = s_inv;
    float4 gv = ((const float4*)g)[t];
    float4 uv = ((const float4*)(U + (size_t)r * D_MODEL))[t];
    float o[4] = {v.x*iv*gv.x*uv.x, v.y*iv*gv.y*uv.y, v.z*iv*gv.z*uv.z, v.w*iv*gv.w*uv.w};
    __nv_bfloat16 h[4], l[4];
    #pragma unroll
    for (int i = 0; i < 4; i++) {
        h[i] = __float2bfloat16(o[i]);
        l[i] = __float2bfloat16(o[i] - __bfloat162float(h[i]));
    }
    size_t base = (size_t)r * D_MODEL + t*4;
    *(__nv_bfloat162*)(Yh + base)     = __nv_bfloat162(h[0], h[1]);
    *(__nv_bfloat162*)(Yh + base + 2) = __nv_bfloat162(h[2], h[3]);
    *(__nv_bfloat162*)(Yl + base)     = __nv_bfloat162(l[0], l[1]);
    *(__nv_bfloat162*)(Yl + base + 2) = __nv_bfloat162(l[2], l[3]);
}

// -------- swiglu -> bf16 hi/lo ----------------------------------------------
__global__ void __launch_bounds__(256)
swiglu_tc(const float* __restrict__ X12,
          __nv_bfloat16* __restrict__ Yh, __nv_bfloat16* __restrict__ Yl)
{
    int i4 = blockIdx.x * blockDim.x + threadIdx.x;
    int r  = i4 >> 8;
    int c4 = i4 & 255;
    float4 a = ((const float4*)(X12 + (size_t)r * 2048))[c4];
    float4 b = ((const float4*)(X12 + (size_t)r * 2048 + 1024))[c4];
    float o[4] = {siluf(a.x)*b.x, siluf(a.y)*b.y, siluf(a.z)*b.z, siluf(a.w)*b.w};
    __nv_bfloat16 h[4], l[4];
    #pragma unroll
    for (int i = 0; i < 4; i++) {
        h[i] = __float2bfloat16(o[i]);
        l[i] = __float2bfloat16(o[i] - __bfloat162float(h[i]));
    }
    size_t base = (size_t)r * 1024 + c4*4;
    *(__nv_bfloat162*)(Yh + base)     = __nv_bfloat162(h[0], h[1]);
    *(__nv_bfloat162*)(Yh + base + 2) = __nv_bfloat162(h[2], h[3]);
    *(__nv_bfloat162*)(Yl + base)     = __nv_bfloat162(l[0], l[1]);
    *(__nv_bfloat162*)(Yl + base + 2) = __nv_bfloat162(l[2], l[3]);
}

// ============== HMMA GEMM: C = (Ah+Al)[M,K] @ (Bh+Bl)[N,K]^T + bias =========
// BM=128, BN=256, BK=64. 512 threads = 16 warps (2 M x 8 N), warp tile 64x32.
// 3 passes: hi*hi + hi*lo + lo*hi. 2-stage cp.async pipeline, SW128 swizzle.
// EPI: 0 = bias, 1 = silu(acc+bias), 2 = acc+bias+R
#define SM_A_HI 0
#define SM_A_LO 16384
#define SM_B_HI 32768
#define SM_B_LO 65536
#define STAGE_B 98304

template<int EPI>
__global__ void __launch_bounds__(512, 1)
gemm_hmma(const __nv_bfloat16* __restrict__ Ah, const __nv_bfloat16* __restrict__ Al,
          const __nv_bfloat16* __restrict__ Bh, const __nv_bfloat16* __restrict__ Bl,
          const float* __restrict__ bias, const float* __restrict__ R,
          float* __restrict__ C, int M, int N, int K)
{
    extern __shared__ __align__(128) char sm[];
    uint32_t sb = smem_u32(sm);
    int tid  = threadIdx.x;
    int wid  = tid >> 5;
    int lane = tid & 31;
    int wm = wid & 1, wn = wid >> 1;           // 2 x 8 warp grid
    int bm = blockIdx.y * 128, bn = blockIdx.x * 256;
    int m0 = wm * 64, n0 = wn * 32;

    int laneRow = lane & 15;
    int laneK   = (lane >> 4) * 16;
    uint32_t xorA = (uint32_t)((laneRow & 7) << 4);

    float acc[4][4][4];
    #pragma unroll
    for (int i = 0; i < 4; i++)
        #pragma unroll
        for (int j = 0; j < 4; j++)
            #pragma unroll
            for (int q = 0; q < 4; q++) acc[i][j][q] = 0.f;

    const int NCH = K >> 6;   // 16

    auto load_stage = [&](int s, int chunk) {
        uint32_t st = sb + s * STAGE_B;
        int k0 = chunk * 64;
        // A hi/lo: 128 rows x 128B
        #pragma unroll
        for (int it = 0; it < 2; it++) {
            int idx = tid + it * 512;
            int row = idx >> 3, c = idx & 7;
            uint32_t d = st + row * 128 + (uint32_t)((c * 16) ^ ((row & 7) << 4));
            size_t go = (size_t)(bm + row) * K + k0 + c * 8;
            cp16(d + SM_A_HI, Ah + go);
            cp16(d + SM_A_LO, Al + go);
        }
        // B hi/lo: 256 rows x 128B
        #pragma unroll
        for (int it = 0; it < 4; it++) {
            int idx = tid + it * 512;
            int row = idx >> 3, c = idx & 7;
            uint32_t d = st + row * 128 + (uint32_t)((c * 16) ^ ((row & 7) << 4));
            size_t go = (size_t)(bn + row) * K + k0 + c * 8;
            cp16(d + SM_B_HI, Bh + go);
            cp16(d + SM_B_LO, Bl + go);
        }
    };

    load_stage(0, 0);
    cp_commit();

    for (int chunk = 0; chunk < NCH; chunk++) {
        int s = chunk & 1;
        if (chunk + 1 < NCH) {
            load_stage(s ^ 1, chunk + 1);
            cp_commit();
            cp_wait1();
        } else {
            cp_wait0();
        }
        __syncthreads();

        uint32_t st = sb + s * STAGE_B;
        #pragma unroll
        for (int pass = 0; pass < 3; pass++) {
            uint32_t Abase = st + (pass == 2 ? SM_A_LO : SM_A_HI);
            uint32_t Bbase = st + (pass == 1 ? SM_B_LO : SM_B_HI);
            #pragma unroll
            for (int ks = 0; ks < 4; ks++) {
                uint32_t kb = (uint32_t)((ks * 32 + laneK) ^ xorA);
                uint32_t a[4][4];
                #pragma unroll
                for (int i = 0; i < 4; i++)
                    ldsm_x4(a[i], Abase + (uint32_t)(m0 + i*16 + laneRow) * 128 + kb);
                uint32_t b[2][4];
                #pragma unroll
                for (int p = 0; p < 2; p++)
                    ldsm_x4(b[p], Bbase + (uint32_t)(n0 + p*16 + laneRow) * 128 + kb);
                #pragma unroll
                for (int i = 0; i < 4; i++)
                    #pragma unroll
                    for (int j = 0; j < 4; j++)
                        mma16816(acc[i][j], a[i], b[j>>1][j&1], b[j>>1][2 + (j&1)]);
            }
        }
        __syncthreads();
    }

    // ---- epilogue ----
    int group = lane >> 2, tq = lane & 3;
    #pragma unroll
    for (int j = 0; j < 4; j++) {
        int n = bn + n0 + j*8 + tq*2;
        float bv0 = bias[n], bv1 = bias[n+1];
        #pragma unroll
        for (int i = 0; i < 4; i++) {
            int m = bm + m0 + i*16 + group;
            size_t off0 = (size_t)m * N + n;
            size_t off1 = (size_t)(m + 8) * N + n;
            float v0 = acc[i][j][0] + bv0, v1 = acc[i][j][1] + bv1;
            float v2 = acc[i][j][2] + bv0, v3 = acc[i][j][3] + bv1;
            if (EPI == 1) { v0 = siluf(v0); v1 = siluf(v1); v2 = siluf(v2); v3 = siluf(v3); }
            if (EPI == 2) {
                float2 r0 = *(const float2*)(R + off0);
                float2 r1 = *(const float2*)(R + off1);
                v0 += r0.x; v1 += r0.y; v2 += r1.x; v3 += r1.y;
            }
            *(float2*)(C + off0) = make_float2(v0, v1);
            *(float2*)(C + off1) = make_float2(v2, v3);
        }
    }
}

// ---------------- fused SiLU-attention (SIMT fp32, proven) ------------------
__global__ void __launch_bounds__(256)
attn_k(const float* __restrict__ Q, const float* __restrict__ K,
       const float* __restrict__ V, const float* __restrict__ PB,
       float* __restrict__ O)
{
    extern __shared__ float smf[];
    float* qT  = smf;
    float* kT  = smf + 4352;
    float* sS  = smf + 2*4352;
    float* vS  = smf + 3*4352;
    float* pbs = smf + 4*4352;

    int tid = threadIdx.x;
    int tx = tid & 15, ty = tid >> 4;
    int qt = blockIdx.x, h = blockIdx.y, b = blockIdx.z;
    size_t headOff = (size_t)h * DH;

    {
        int r  = tid & 63;
        int cb = (tid >> 6) << 4;
        const float* qp = Q + ((size_t)(b*SEQ + qt*64 + r)) * D_MODEL + headOff + cb;
        #pragma unroll
        for (int it = 0; it < 4; it++) {
            float4 a = *(const float4*)(qp + it*4);
            int c = cb + it*4;
            qT[(c+0)*68 + r] = a.x; qT[(c+1)*68 + r] = a.y;
            qT[(c+2)*68 + r] = a.z; qT[(c+3)*68 + r] = a.w;
        }
    }

    float acc[4][4];
    #pragma unroll
    for (int i = 0; i < 4; i++)
        #pragma unroll
        for (int j = 0; j < 4; j++) acc[i][j] = 0.f;

    for (int kt = 0; kt < SEQ/64; kt++) {
        __syncthreads();
        {
            int r  = tid & 63;
            int cb = (tid >> 6) << 4;
            const float* kp = K + ((size_t)(b*SEQ + kt*64 + r)) * D_MODEL + headOff + cb;
            #pragma unroll
            for (int it = 0; it < 4; it++) {
                float4 a = *(const float4*)(kp + it*4);
                int c = cb + it*4;
                kT[(c+0)*68 + r] = a.x; kT[(c+1)*68 + r] = a.y;
                kT[(c+2)*68 + r] = a.z; kT[(c+3)*68 + r] = a.w;
            }
        }
        #pragma unroll
        for (int it = 0; it < 4; it++) {
            int L = tid*4 + it*1024;
            int tr = L >> 6, tc = L & 63;
            float4 a = *(const float4*)(V + ((size_t)(b*SEQ + kt*64 + tr)) * D_MODEL + headOff + tc);
            *(float4*)&vS[tr*68 + tc] = a;
        }
        if (tid < 64) pbs[tid] = PB[(size_t)(kt*64 + tid) * N_HEADS + h];
        __syncthreads();

        float s[4][4];
        #pragma unroll
        for (int i = 0; i < 4; i++)
            #pragma unroll
            for (int j = 0; j < 4; j++) s[i][j] = 0.f;
        #pragma unroll 8
        for (int kk = 0; kk < 64; kk++) {
            float4 a4 = *(const float4*)&qT[kk*68 + ty*4];
            float4 b4 = *(const float4*)&kT[kk*68 + tx*4];
            float av[4] = {a4.x, a4.y, a4.z, a4.w};
            float bv[4] = {b4.x, b4.y, b4.z, b4.w};
            #pragma unroll
            for (int i = 0; i < 4; i++)
                #pragma unroll
                for (int j = 0; j < 4; j++)
                    s[i][j] = fmaf(av[i], bv[j], s[i][j]);
        }
        #pragma unroll
        for (int i = 0; i < 4; i++)
            #pragma unroll
            for (int j = 0; j < 4; j++) {
                float z = s[i][j] * 0.125f + pbs[tx*4 + j];
                sS[(ty*4 + i)*68 + tx*4 + j] = siluf(z);
            }
        __syncthreads();

        #pragma unroll 8
        for (int t = 0; t < 64; t++) {
            float a0 = sS[(ty*4 + 0)*68 + t];
            float a1 = sS[(ty*4 + 1)*68 + t];
            float a2 = sS[(ty*4 + 2)*68 + t];
            float a3 = sS[(ty*4 + 3)*68 + t];
            float4 b4 = *(const float4*)&vS[t*68 + tx*4];
            float bv[4] = {b4.x, b4.y, b4.z, b4.w};
            #pragma unroll
            for (int j = 0; j < 4; j++) {
                acc[0][j] = fmaf(a0, bv[j], acc[0][j]);
                acc[1][j] = fmaf(a1, bv[j], acc[1][j]);
                acc[2][j] = fmaf(a2, bv[j], acc[2][j]);
                acc[3][j] = fmaf(a3, bv[j], acc[3][j]);
            }
        }
    }

    #pragma unroll
    for (int i = 0; i < 4; i++) {
        size_t off = ((size_t)(b*SEQ + qt*64 + ty*4 + i)) * D_MODEL + headOff + tx*4;
        *(float4*)&O[off] = make_float4(acc[i][0], acc[i][1], acc[i][2], acc[i][3]);
    }
}

// ---------------- launch ----------------------------------------------------
extern "C" void kernel_launch(void* const* d_in, const int* in_sizes, int n_in,
                              void* d_out, int out_size)
{
    const float* x      = (const float*)d_in[0];
    const float* pb     = (const float*)d_in[2];
    const float* wq     = (const float*)d_in[3];
    const float* bq     = (const float*)d_in[4];
    const float* wk     = (const float*)d_in[5];
    const float* bk_    = (const float*)d_in[6];
    const float* wv     = (const float*)d_in[7];
    const float* bv     = (const float*)d_in[8];
    const float* wu     = (const float*)d_in[9];
    const float* bu     = (const float*)d_in[10];
    const float* g_ams  = (const float*)d_in[11];
    const float* w0     = (const float*)d_in[12];
    const float* b0     = (const float*)d_in[13];
    const float* w1     = (const float*)d_in[14];
    const float* b1     = (const float*)d_in[15];
    const float* w2     = (const float*)d_in[16];
    const float* b2     = (const float*)d_in[17];
    const float* g_mffn = (const float*)d_in[18];
    float* out = (float*)d_out;

    float *Qf, *Kf, *Vf, *Uf, *AOf, *Of, *X12;
    __nv_bfloat16 *A1h, *A1l, *A2h, *A2l, *WTh, *WTl;
    cudaGetSymbolAddress((void**)&Qf,  g_Q);
    cudaGetSymbolAddress((void**)&Kf,  g_K);
    cudaGetSymbolAddress((void**)&Vf,  g_V);
    cudaGetSymbolAddress((void**)&Uf,  g_U);
    cudaGetSymbolAddress((void**)&AOf, g_AO);
    cudaGetSymbolAddress((void**)&Of,  g_O);
    cudaGetSymbolAddress((void**)&X12, g_X12);
    cudaGetSymbolAddress((void**)&A1h, g_A1h);
    cudaGetSymbolAddress((void**)&A1l, g_A1l);
    cudaGetSymbolAddress((void**)&A2h, g_A2h);
    cudaGetSymbolAddress((void**)&A2l, g_A2l);
    cudaGetSymbolAddress((void**)&WTh, g_WTh);
    cudaGetSymbolAddress((void**)&WTl, g_WTl);

    const size_t W1M = (size_t)1024*1024;
    __nv_bfloat16 *Tq_h = WTh + 0*W1M, *Tq_l = WTl + 0*W1M;
    __nv_bfloat16 *Tk_h = WTh + 1*W1M, *Tk_l = WTl + 1*W1M;
    __nv_bfloat16 *Tv_h = WTh + 2*W1M, *Tv_l = WTl + 2*W1M;
    __nv_bfloat16 *Tu_h = WTh + 3*W1M, *Tu_l = WTl + 3*W1M;
    __nv_bfloat16 *T0_h = WTh + 4*W1M, *T0_l = WTl + 4*W1M;
    __nv_bfloat16 *T2_h = WTh + 5*W1M, *T2_l = WTl + 5*W1M;
    __nv_bfloat16 *T1_h = WTh + 6*W1M, *T1_l = WTl + 6*W1M;

    const int GSM = 2 * STAGE_B;   // 196608
    cudaFuncSetAttribute(attn_k, cudaFuncAttributeMaxDynamicSharedMemorySize, 69888);
    cudaFuncSetAttribute(gemm_hmma<0>, cudaFuncAttributeMaxDynamicSharedMemorySize, GSM);
    cudaFuncSetAttribute(gemm_hmma<1>, cudaFuncAttributeMaxDynamicSharedMemorySize, GSM);
    cudaFuncSetAttribute(gemm_hmma<2>, cudaFuncAttributeMaxDynamicSharedMemorySize, GSM);

    dim3 tb(32, 8);
    dim3 tg(32, 32);
    dim3 tg1(64, 32);

    wtsplit_k<<<tg,  tb>>>(wq, Tq_h, Tq_l, 1024, 1024);
    wtsplit_k<<<tg,  tb>>>(wk, Tk_h, Tk_l, 1024, 1024);
    wtsplit_k<<<tg,  tb>>>(wv, Tv_h, Tv_l, 1024, 1024);
    wtsplit_k<<<tg,  tb>>>(wu, Tu_h, Tu_l, 1024, 1024);
    wtsplit_k<<<tg,  tb>>>(w0, T0_h, T0_l, 1024, 1024);
    wtsplit_k<<<tg,  tb>>>(w2, T2_h, T2_l, 1024, 1024);
    wtsplit_k<<<tg1, tb>>>(w1, T1_h, T1_l, 1024, 2048);

    dim3 gP(4, 32);    // N=1024: 128 CTAs
    dim3 gW1(8, 32);   // N=2048: 256 CTAs

    rmsnorm_tc<<<M_ROWS, 256>>>(x, g_ams, A1h, A1l);
    gemm_hmma<0><<<gP, 512, GSM>>>(A1h, A1l, Tq_h, Tq_l, bq,  nullptr, Qf, M_ROWS, 1024, 1024);
    gemm_hmma<0><<<gP, 512, GSM>>>(A1h, A1l, Tk_h, Tk_l, bk_, nullptr, Kf, M_ROWS, 1024, 1024);
    gemm_hmma<0><<<gP, 512, GSM>>>(A1h, A1l, Tv_h, Tv_l, bv,  nullptr, Vf, M_ROWS, 1024, 1024);
    gemm_hmma<1><<<gP, 512, GSM>>>(A1h, A1l, Tu_h, Tu_l, bu,  nullptr, Uf, M_ROWS, 1024, 1024);
    attn_k<<<dim3(SEQ/64, N_HEADS, BATCH), 256, 69888>>>(Qf, Kf, Vf, pb, AOf);
    ams_tc<<<M_ROWS, 256>>>(AOf, g_ams, Uf, A2h, A2l);
    gemm_hmma<2><<<gP, 512, GSM>>>(A2h, A2l, T0_h, T0_l, b0, x, Of, M_ROWS, 1024, 1024);
    rmsnorm_tc<<<M_ROWS, 256>>>(Of, g_mffn, A1h, A1l);
    gemm_hmma<0><<<gW1, 512, GSM>>>(A1h, A1l, T1_h, T1_l, b1, nullptr, X12, M_ROWS, 2048, 1024);
    swiglu_tc<<<4096, 256>>>(X12, A2h, A2l);
    gemm_hmma<2><<<gP, 512, GSM>>>(A2h, A2l, T2_h, T2_l, b2, Of, out, M_ROWS, 1024, 1024);
}

// round 5
// speedup vs baseline: 1.7351x; 1.2423x over previous
#include <cuda_runtime.h>
#include <cuda_bf16.h>
#include <cstdint>
#include <math.h>

#define D_MODEL 1024
#define N_HEADS 16
#define DH      64
#define BATCH   2
#define SEQ     2048
#define M_ROWS  (BATCH*SEQ)   // 4096

// ---------------- scratch (static device globals; no allocations) ----------
__device__ float g_Q  [M_ROWS*D_MODEL];   // aliased: Qh/Ql bf16
__device__ float g_K  [M_ROWS*D_MODEL];   // aliased: Kh/Kl bf16
__device__ float g_V  [M_ROWS*D_MODEL];   // aliased: VTh/VTl bf16 (transposed per head)
__device__ float g_U  [M_ROWS*D_MODEL];
__device__ float g_AO [M_ROWS*D_MODEL];
__device__ float g_O  [M_ROWS*D_MODEL];
__device__ float g_X12[M_ROWS*2*D_MODEL];

__device__ __nv_bfloat16 g_A1h[M_ROWS*D_MODEL];
__device__ __nv_bfloat16 g_A1l[M_ROWS*D_MODEL];
__device__ __nv_bfloat16 g_A2h[M_ROWS*D_MODEL];
__device__ __nv_bfloat16 g_A2l[M_ROWS*D_MODEL];

__device__ __nv_bfloat16 g_WTh[8*1024*1024];
__device__ __nv_bfloat16 g_WTl[8*1024*1024];

__device__ __forceinline__ float siluf(float z) {
    return z * (1.0f / (1.0f + __expf(-z)));
}

__device__ __forceinline__ uint32_t smem_u32(const void* p) {
    uint32_t a;
    asm("{ .reg .u64 t; cvta.to.shared.u64 t, %1; cvt.u32.u64 %0, t; }" : "=r"(a) : "l"(p));
    return a;
}

__device__ __forceinline__ void ldsm_x4(uint32_t* r, uint32_t a) {
    asm volatile("ldmatrix.sync.aligned.m8n8.x4.shared.b16 {%0,%1,%2,%3}, [%4];"
                 : "=r"(r[0]), "=r"(r[1]), "=r"(r[2]), "=r"(r[3]) : "r"(a));
}

__device__ __forceinline__ void mma16816(float* c, const uint32_t* a, uint32_t b0, uint32_t b1) {
    asm volatile("mma.sync.aligned.m16n8k16.row.col.f32.bf16.bf16.f32 "
                 "{%0,%1,%2,%3}, {%4,%5,%6,%7}, {%8,%9}, {%0,%1,%2,%3};"
                 : "+f"(c[0]), "+f"(c[1]), "+f"(c[2]), "+f"(c[3])
                 : "r"(a[0]), "r"(a[1]), "r"(a[2]), "r"(a[3]), "r"(b0), "r"(b1));
}

__device__ __forceinline__ void cp16(uint32_t dst, const void* src) {
    asm volatile("cp.async.cg.shared.global [%0], [%1], 16;" :: "r"(dst), "l"(src));
}
__device__ __forceinline__ void cp_commit() { asm volatile("cp.async.commit_group;"); }
__device__ __forceinline__ void cp_wait1()  { asm volatile("cp.async.wait_group 1;"); }
__device__ __forceinline__ void cp_wait0()  { asm volatile("cp.async.wait_group 0;"); }

__device__ __forceinline__ void split_bf16(float v, __nv_bfloat16& h, __nv_bfloat16& l) {
    h = __float2bfloat16(v);
    l = __float2bfloat16(v - __bfloat162float(h));
}

// ============ weight transpose + bf16 split: W[K,N] -> T[N,K] hi/lo ========
__global__ void __launch_bounds__(256)
wtsplit_k(const float* __restrict__ W, __nv_bfloat16* __restrict__ Thi,
          __nv_bfloat16* __restrict__ Tlo, int K, int N)
{
    __shared__ float t[32][33];
    int tx = threadIdx.x, ty = threadIdx.y;
    int n0 = blockIdx.x * 32, k0 = blockIdx.y * 32;
    #pragma unroll
    for (int i = 0; i < 4; i++)
        t[ty + i*8][tx] = W[(size_t)(k0 + ty + i*8) * N + n0 + tx];
    __syncthreads();
    #pragma unroll
    for (int i = 0; i < 4; i++) {
        float v = t[tx][ty + i*8];
        __nv_bfloat16 hi, lo;
        split_bf16(v, hi, lo);
        size_t off = (size_t)(n0 + ty + i*8) * K + k0 + tx;
        Thi[off] = hi; Tlo[off] = lo;
    }
}

// ---------------- RMSNorm -> bf16 hi/lo -------------------------------------
__global__ void __launch_bounds__(256)
rmsnorm_tc(const float* __restrict__ X, const float* __restrict__ g,
           __nv_bfloat16* __restrict__ Yh, __nv_bfloat16* __restrict__ Yl)
{
    int r = blockIdx.x, t = threadIdx.x;
    float4 v = ((const float4*)(X + (size_t)r * D_MODEL))[t];
    float ss = v.x*v.x + v.y*v.y + v.z*v.z + v.w*v.w;
    #pragma unroll
    for (int o = 16; o; o >>= 1) ss += __shfl_xor_sync(0xffffffffu, ss, o);
    __shared__ float ws[8]; __shared__ float s_inv;
    if ((t & 31) == 0) ws[t >> 5] = ss;
    __syncthreads();
    if (t == 0) {
        float tot = 0.f;
        #pragma unroll
        for (int i = 0; i < 8; i++) tot += ws[i];
        s_inv = rsqrtf(tot * (1.0f / D_MODEL) + 1e-8f);
    }
    __syncthreads();
    float iv = s_inv;
    float4 gv = ((const float4*)g)[t];
    float o[4] = {v.x*iv*gv.x, v.y*iv*gv.y, v.z*iv*gv.z, v.w*iv*gv.w};
    __nv_bfloat16 h[4], l[4];
    #pragma unroll
    for (int i = 0; i < 4; i++) split_bf16(o[i], h[i], l[i]);
    size_t base = (size_t)r * D_MODEL + t*4;
    *(__nv_bfloat162*)(Yh + base)     = __nv_bfloat162(h[0], h[1]);
    *(__nv_bfloat162*)(Yh + base + 2) = __nv_bfloat162(h[2], h[3]);
    *(__nv_bfloat162*)(Yl + base)     = __nv_bfloat162(l[0], l[1]);
    *(__nv_bfloat162*)(Yl + base + 2) = __nv_bfloat162(l[2], l[3]);
}

// -------- ams: out = rmsnorm(A, g) * U -> bf16 hi/lo ------------------------
__global__ void __launch_bounds__(256)
ams_tc(const float* __restrict__ A, const float* __restrict__ g,
       const float* __restrict__ U,
       __nv_bfloat16* __restrict__ Yh, __nv_bfloat16* __restrict__ Yl)
{
    int r = blockIdx.x, t = threadIdx.x;
    float4 v = ((const float4*)(A + (size_t)r * D_MODEL))[t];
    float ss = v.x*v.x + v.y*v.y + v.z*v.z + v.w*v.w;
    #pragma unroll
    for (int o = 16; o; o >>= 1) ss += __shfl_xor_sync(0xffffffffu, ss, o);
    __shared__ float ws[8]; __shared__ float s_inv;
    if ((t & 31) == 0) ws[t >> 5] = ss;
    __syncthreads();
    if (t == 0) {
        float tot = 0.f;
        #pragma unroll
        for (int i = 0; i < 8; i++) tot += ws[i];
        s_inv = rsqrtf(tot * (1.0f / D_MODEL) + 1e-8f);
    }
    __syncthreads();
    float iv = s_inv;
    float4 gv = ((const float4*)g)[t];
    float4 uv = ((const float4*)(U + (size_t)r * D_MODEL))[t];
    float o[4] = {v.x*iv*gv.x*uv.x, v.y*iv*gv.y*uv.y, v.z*iv*gv.z*uv.z, v.w*iv*gv.w*uv.w};
    __nv_bfloat16 h[4], l[4];
    #pragma unroll
    for (int i = 0; i < 4; i++) split_bf16(o[i], h[i], l[i]);
    size_t base = (size_t)r * D_MODEL + t*4;
    *(__nv_bfloat162*)(Yh + base)     = __nv_bfloat162(h[0], h[1]);
    *(__nv_bfloat162*)(Yh + base + 2) = __nv_bfloat162(h[2], h[3]);
    *(__nv_bfloat162*)(Yl + base)     = __nv_bfloat162(l[0], l[1]);
    *(__nv_bfloat162*)(Yl + base + 2) = __nv_bfloat162(l[2], l[3]);
}

// -------- swiglu -> bf16 hi/lo ----------------------------------------------
__global__ void __launch_bounds__(256)
swiglu_tc(const float* __restrict__ X12,
          __nv_bfloat16* __restrict__ Yh, __nv_bfloat16* __restrict__ Yl)
{
    int i4 = blockIdx.x * blockDim.x + threadIdx.x;
    int r  = i4 >> 8;
    int c4 = i4 & 255;
    float4 a = ((const float4*)(X12 + (size_t)r * 2048))[c4];
    float4 b = ((const float4*)(X12 + (size_t)r * 2048 + 1024))[c4];
    float o[4] = {siluf(a.x)*b.x, siluf(a.y)*b.y, siluf(a.z)*b.z, siluf(a.w)*b.w};
    __nv_bfloat16 h[4], l[4];
    #pragma unroll
    for (int i = 0; i < 4; i++) split_bf16(o[i], h[i], l[i]);
    size_t base = (size_t)r * 1024 + c4*4;
    *(__nv_bfloat162*)(Yh + base)     = __nv_bfloat162(h[0], h[1]);
    *(__nv_bfloat162*)(Yh + base + 2) = __nv_bfloat162(h[2], h[3]);
    *(__nv_bfloat162*)(Yl + base)     = __nv_bfloat162(l[0], l[1]);
    *(__nv_bfloat162*)(Yl + base + 2) = __nv_bfloat162(l[2], l[3]);
}

// ============== HMMA GEMM: C = (Ah+Al)[M,K] @ (Bh+Bl)[N,K]^T + bias =========
// EPI: 0 bias->f32, 1 silu->f32, 2 bias+R->f32, 3 bias->bf16 hi/lo,
//      4 bias->bf16 hi/lo transposed per head (VT[b,h][d][t])
#define SM_A_HI 0
#define SM_A_LO 16384
#define SM_B_HI 32768
#define SM_B_LO 65536
#define STAGE_B 98304

template<int EPI>
__global__ void __launch_bounds__(512, 1)
gemm_hmma(const __nv_bfloat16* __restrict__ Ah, const __nv_bfloat16* __restrict__ Al,
          const __nv_bfloat16* __restrict__ Bh, const __nv_bfloat16* __restrict__ Bl,
          const float* __restrict__ bias, const float* __restrict__ R,
          float* __restrict__ C, __nv_bfloat16* __restrict__ Yh,
          __nv_bfloat16* __restrict__ Yl, int M, int N, int K)
{
    extern __shared__ __align__(128) char sm[];
    uint32_t sb = smem_u32(sm);
    int tid  = threadIdx.x;
    int wid  = tid >> 5;
    int lane = tid & 31;
    int wm = wid & 1, wn = wid >> 1;
    int bm = blockIdx.y * 128, bn = blockIdx.x * 256;
    int m0 = wm * 64, n0 = wn * 32;

    int laneRow = lane & 15;
    int laneK   = (lane >> 4) * 16;
    uint32_t xorA = (uint32_t)((laneRow & 7) << 4);

    float acc[4][4][4];
    #pragma unroll
    for (int i = 0; i < 4; i++)
        #pragma unroll
        for (int j = 0; j < 4; j++)
            #pragma unroll
            for (int q = 0; q < 4; q++) acc[i][j][q] = 0.f;

    const int NCH = K >> 6;

    auto load_stage = [&](int s, int chunk) {
        uint32_t st = sb + s * STAGE_B;
        int k0 = chunk * 64;
        #pragma unroll
        for (int it = 0; it < 2; it++) {
            int idx = tid + it * 512;
            int row = idx >> 3, c = idx & 7;
            uint32_t d = st + row * 128 + (uint32_t)((c * 16) ^ ((row & 7) << 4));
            size_t go = (size_t)(bm + row) * K + k0 + c * 8;
            cp16(d + SM_A_HI, Ah + go);
            cp16(d + SM_A_LO, Al + go);
        }
        #pragma unroll
        for (int it = 0; it < 4; it++) {
            int idx = tid + it * 512;
            int row = idx >> 3, c = idx & 7;
            uint32_t d = st + row * 128 + (uint32_t)((c * 16) ^ ((row & 7) << 4));
            size_t go = (size_t)(bn + row) * K + k0 + c * 8;
            cp16(d + SM_B_HI, Bh + go);
            cp16(d + SM_B_LO, Bl + go);
        }
    };

    load_stage(0, 0);
    cp_commit();

    for (int chunk = 0; chunk < NCH; chunk++) {
        int s = chunk & 1;
        if (chunk + 1 < NCH) {
            load_stage(s ^ 1, chunk + 1);
            cp_commit();
            cp_wait1();
        } else {
            cp_wait0();
        }
        __syncthreads();

        uint32_t st = sb + s * STAGE_B;
        #pragma unroll
        for (int pass = 0; pass < 3; pass++) {
            uint32_t Abase = st + (pass == 2 ? SM_A_LO : SM_A_HI);
            uint32_t Bbase = st + (pass == 1 ? SM_B_LO : SM_B_HI);
            #pragma unroll
            for (int ks = 0; ks < 4; ks++) {
                uint32_t kb = (uint32_t)((ks * 32 + laneK) ^ xorA);
                uint32_t a[4][4];
                #pragma unroll
                for (int i = 0; i < 4; i++)
                    ldsm_x4(a[i], Abase + (uint32_t)(m0 + i*16 + laneRow) * 128 + kb);
                uint32_t b[2][4];
                #pragma unroll
                for (int p = 0; p < 2; p++)
                    ldsm_x4(b[p], Bbase + (uint32_t)(n0 + p*16 + laneRow) * 128 + kb);
                #pragma unroll
                for (int i = 0; i < 4; i++)
                    #pragma unroll
                    for (int j = 0; j < 4; j++)
                        mma16816(acc[i][j], a[i], b[j>>1][j&1], b[j>>1][2 + (j&1)]);
            }
        }
        __syncthreads();
    }

    // ---- epilogue ----
    int group = lane >> 2, tq = lane & 3;
    #pragma unroll
    for (int j = 0; j < 4; j++) {
        int n = bn + n0 + j*8 + tq*2;
        float bv0 = bias[n], bv1 = bias[n+1];
        #pragma unroll
        for (int i = 0; i < 4; i++) {
            int m = bm + m0 + i*16 + group;
            float v0 = acc[i][j][0] + bv0, v1 = acc[i][j][1] + bv1;
            float v2 = acc[i][j][2] + bv0, v3 = acc[i][j][3] + bv1;
            if (EPI == 1) { v0 = siluf(v0); v1 = siluf(v1); v2 = siluf(v2); v3 = siluf(v3); }
            if (EPI <= 2) {
                size_t off0 = (size_t)m * N + n;
                size_t off1 = (size_t)(m + 8) * N + n;
                if (EPI == 2) {
                    float2 r0 = *(const float2*)(R + off0);
                    float2 r1 = *(const float2*)(R + off1);
                    v0 += r0.x; v1 += r0.y; v2 += r1.x; v3 += r1.y;
                }
                *(float2*)(C + off0) = make_float2(v0, v1);
                *(float2*)(C + off1) = make_float2(v2, v3);
            } else if (EPI == 3) {
                __nv_bfloat16 h0,l0,h1,l1,h2,l2,h3,l3;
                split_bf16(v0,h0,l0); split_bf16(v1,h1,l1);
                split_bf16(v2,h2,l2); split_bf16(v3,h3,l3);
                size_t off0 = (size_t)m * N + n;
                size_t off1 = (size_t)(m + 8) * N + n;
                *(__nv_bfloat162*)(Yh + off0) = __nv_bfloat162(h0, h1);
                *(__nv_bfloat162*)(Yl + off0) = __nv_bfloat162(l0, l1);
                *(__nv_bfloat162*)(Yh + off1) = __nv_bfloat162(h2, h3);
                *(__nv_bfloat162*)(Yl + off1) = __nv_bfloat162(l2, l3);
            } else {  // EPI == 4: VT[b,h][d][t]
                __nv_bfloat16 h0,l0,h1,l1,h2,l2,h3,l3;
                split_bf16(v0,h0,l0); split_bf16(v1,h1,l1);
                split_bf16(v2,h2,l2); split_bf16(v3,h3,l3);
                int bi = m >> 11, tt = m & 2047;
                int hh = n >> 6,  dd = n & 63;
                size_t vb = ((size_t)((bi*16 + hh)*64 + dd)) * 2048 + tt;
                Yh[vb]          = h0;  Yl[vb]          = l0;
                Yh[vb + 2048]   = h1;  Yl[vb + 2048]   = l1;
                Yh[vb + 8]      = h2;  Yl[vb + 8]      = l2;
                Yh[vb + 2056]   = h3;  Yl[vb + 2056]   = l3;
            }
        }
    }
}

// ================= tensor-core fused SiLU-attention ==========================
// grid (SEQ/128, H, B), 256 threads. S = QK^T (3-pass), silu -> smem hi/lo,
// O += S@V via VT (3-pass). K/VT double-buffered cp.async.
#define A_SQH 0u
#define A_SQL 16384u
#define A_SK  32768u       // + s*32768 : KH, KL(+16384)
#define A_SVT 98304u       // + s*32768 : VTH, VTL(+16384)
#define A_SS  163840u      // SH, SL(+32768)
#define ATT_SMEM 229376

__global__ void __launch_bounds__(256, 1)
attn_tc(const __nv_bfloat16* __restrict__ Qh, const __nv_bfloat16* __restrict__ Ql,
        const __nv_bfloat16* __restrict__ Kh, const __nv_bfloat16* __restrict__ Kl,
        const __nv_bfloat16* __restrict__ VTh, const __nv_bfloat16* __restrict__ VTl,
        const float* __restrict__ PB, float* __restrict__ O)
{
    extern __shared__ __align__(128) char sm[];
    uint32_t sb = smem_u32(sm);
    int tid  = threadIdx.x;
    int wid  = tid >> 5;
    int lane = tid & 31;
    int wm = wid & 1, wn = wid >> 1;
    int qt = blockIdx.x, h = blockIdx.y, b = blockIdx.z;
    int m0 = wm * 64, nS0 = wn * 32, nO0 = wn * 16;

    int laneRow = lane & 15;
    int laneK   = (lane >> 4) * 16;
    uint32_t xorA = (uint32_t)((laneRow & 7) << 4);
    int group = lane >> 2, tq = lane & 3;

    // ---- loaders ----
    auto load_q = [&]() {
        #pragma unroll
        for (int it = 0; it < 4; it++) {
            int idx = tid + it * 256;
            int row = idx >> 3, c = idx & 7;
            uint32_t d = row * 128 + (uint32_t)((c * 16) ^ ((row & 7) << 4));
            size_t go = ((size_t)(b*SEQ + qt*128 + row)) * D_MODEL + h*64 + c*8;
            cp16(sb + A_SQH + d, Qh + go);
            cp16(sb + A_SQL + d, Ql + go);
        }
    };
    auto load_kv = [&](int s, int kt) {
        uint32_t kbase = sb + A_SK + (uint32_t)s * 32768u;
        #pragma unroll
        for (int it = 0; it < 4; it++) {
            int idx = tid + it * 256;
            int row = idx >> 3, c = idx & 7;
            uint32_t d = row * 128 + (uint32_t)((c * 16) ^ ((row & 7) << 4));
            size_t go = ((size_t)(b*SEQ + kt*128 + row)) * D_MODEL + h*64 + c*8;
            cp16(kbase + d, Kh + go);
            cp16(kbase + 16384u + d, Kl + go);
        }
        uint32_t vbase = sb + A_SVT + (uint32_t)s * 32768u;
        #pragma unroll
        for (int it = 0; it < 4; it++) {
            int idx = tid + it * 256;
            int row = idx >> 4, c = idx & 15;
            uint32_t d = row * 256 + (uint32_t)((c * 16) ^ ((row & 7) << 4));
            size_t go = ((size_t)((b*16 + h)*64 + row)) * 2048 + kt*128 + c*8;
            cp16(vbase + d, VTh + go);
            cp16(vbase + 16384u + d, VTl + go);
        }
    };

    float accO[4][2][4];
    #pragma unroll
    for (int i = 0; i < 4; i++)
        #pragma unroll
        for (int j = 0; j < 2; j++)
            #pragma unroll
            for (int q = 0; q < 4; q++) accO[i][j][q] = 0.f;

    load_q();
    load_kv(0, 0);
    cp_commit();

    for (int kt = 0; kt < SEQ/128; kt++) {
        int s = kt & 1;
        if (kt + 1 < SEQ/128) {
            load_kv(s ^ 1, kt + 1);
            cp_commit();
            cp_wait1();
        } else {
            cp_wait0();
        }
        __syncthreads();

        // ---- S = Q @ K^T, 3 passes ----
        float acc[4][4][4];
        #pragma unroll
        for (int i = 0; i < 4; i++)
            #pragma unroll
            for (int j = 0; j < 4; j++)
                #pragma unroll
                for (int q = 0; q < 4; q++) acc[i][j][q] = 0.f;

        uint32_t kst = sb + A_SK + (uint32_t)s * 32768u;
        #pragma unroll
        for (int pass = 0; pass < 3; pass++) {
            uint32_t Ab = sb + (pass == 2 ? A_SQL : A_SQH);
            uint32_t Bb = kst + (pass == 1 ? 16384u : 0u);
            #pragma unroll
            for (int ks = 0; ks < 4; ks++) {
                uint32_t kb = (uint32_t)((ks * 32 + laneK) ^ xorA);
                uint32_t a[4][4];
                #pragma unroll
                for (int i = 0; i < 4; i++)
                    ldsm_x4(a[i], Ab + (uint32_t)(m0 + i*16 + laneRow) * 128 + kb);
                uint32_t bf[2][4];
                #pragma unroll
                for (int p = 0; p < 2; p++)
                    ldsm_x4(bf[p], Bb + (uint32_t)(nS0 + p*16 + laneRow) * 128 + kb);
                #pragma unroll
                for (int i = 0; i < 4; i++)
                    #pragma unroll
                    for (int j = 0; j < 4; j++)
                        mma16816(acc[i][j], a[i], bf[j>>1][j&1], bf[j>>1][2 + (j&1)]);
            }
        }

        // ---- silu(scale*S + pb) -> Ssm hi/lo ----
        #pragma unroll
        for (int j = 0; j < 4; j++) {
            int tl = nS0 + j*8 + tq*2;
            int tg = kt*128 + tl;
            float pb0 = PB[(size_t)tg * N_HEADS + h];
            float pb1 = PB[(size_t)(tg + 1) * N_HEADS + h];
            uint32_t tb = (uint32_t)(tl * 2);
            #pragma unroll
            for (int i = 0; i < 4; i++) {
                int m = m0 + i*16 + group;
                float w0 = siluf(acc[i][j][0] * 0.125f + pb0);
                float w1 = siluf(acc[i][j][1] * 0.125f + pb1);
                float w2 = siluf(acc[i][j][2] * 0.125f + pb0);
                float w3 = siluf(acc[i][j][3] * 0.125f + pb1);
                __nv_bfloat16 h0,l0,h1,l1,h2,l2,h3,l3;
                split_bf16(w0,h0,l0); split_bf16(w1,h1,l1);
                split_bf16(w2,h2,l2); split_bf16(w3,h3,l3);
                uint32_t sw = tb ^ (uint32_t)((m & 7) << 4);   // (m+8)&7 == m&7
                uint32_t a0 = (uint32_t)m * 256 + sw;
                uint32_t a1 = (uint32_t)(m + 8) * 256 + sw;
                *(__nv_bfloat162*)(sm + A_SS + a0)          = __nv_bfloat162(h0, h1);
                *(__nv_bfloat162*)(sm + A_SS + a0 + 32768)  = __nv_bfloat162(l0, l1);
                *(__nv_bfloat162*)(sm + A_SS + a1)          = __nv_bfloat162(h2, h3);
                *(__nv_bfloat162*)(sm + A_SS + a1 + 32768)  = __nv_bfloat162(l2, l3);
            }
        }
        __syncthreads();

        // ---- O += S @ V (A = Ssm, B = VT), 3 passes ----
        uint32_t vst = sb + A_SVT + (uint32_t)s * 32768u;
        #pragma unroll
        for (int pass = 0; pass < 3; pass++) {
            uint32_t Ab = sb + A_SS + (pass == 2 ? 32768u : 0u);
            uint32_t Bb = vst + (pass == 1 ? 16384u : 0u);
            #pragma unroll
            for (int ks = 0; ks < 8; ks++) {
                uint32_t kb = (uint32_t)((ks * 32 + laneK) ^ xorA);
                uint32_t a[4][4];
                #pragma unroll
                for (int i = 0; i < 4; i++)
                    ldsm_x4(a[i], Ab + (uint32_t)(m0 + i*16 + laneRow) * 256 + kb);
                uint32_t bv[4];
                ldsm_x4(bv, Bb + (uint32_t)(nO0 + laneRow) * 256 + kb);
                #pragma unroll
                for (int i = 0; i < 4; i++)
                    #pragma unroll
                    for (int j = 0; j < 2; j++)
                        mma16816(accO[i][j], a[i], bv[j], bv[2 + j]);
            }
        }
        __syncthreads();
    }

    // ---- write O ----
    #pragma unroll
    for (int j = 0; j < 2; j++) {
        int col = h*64 + nO0 + j*8 + tq*2;
        #pragma unroll
        for (int i = 0; i < 4; i++) {
            int row = b*SEQ + qt*128 + m0 + i*16 + group;
            *(float2*)(O + (size_t)row * D_MODEL + col) =
                make_float2(accO[i][j][0], accO[i][j][1]);
            *(float2*)(O + (size_t)(row + 8) * D_MODEL + col) =
                make_float2(accO[i][j][2], accO[i][j][3]);
        }
    }
}

// ---------------- launch ----------------------------------------------------
extern "C" void kernel_launch(void* const* d_in, const int* in_sizes, int n_in,
                              void* d_out, int out_size)
{
    const float* x      = (const float*)d_in[0];
    const float* pb     = (const float*)d_in[2];
    const float* wq     = (const float*)d_in[3];
    const float* bq     = (const float*)d_in[4];
    const float* wk     = (const float*)d_in[5];
    const float* bk_    = (const float*)d_in[6];
    const float* wv     = (const float*)d_in[7];
    const float* bv     = (const float*)d_in[8];
    const float* wu     = (const float*)d_in[9];
    const float* bu     = (const float*)d_in[10];
    const float* g_ams  = (const float*)d_in[11];
    const float* w0     = (const float*)d_in[12];
    const float* b0     = (const float*)d_in[13];
    const float* w1     = (const float*)d_in[14];
    const float* b1     = (const float*)d_in[15];
    const float* w2     = (const float*)d_in[16];
    const float* b2     = (const float*)d_in[17];
    const float* g_mffn = (const float*)d_in[18];
    float* out = (float*)d_out;

    float *Qf, *Kf, *Vf, *Uf, *AOf, *Of, *X12;
    __nv_bfloat16 *A1h, *A1l, *A2h, *A2l, *WTh, *WTl;
    cudaGetSymbolAddress((void**)&Qf,  g_Q);
    cudaGetSymbolAddress((void**)&Kf,  g_K);
    cudaGetSymbolAddress((void**)&Vf,  g_V);
    cudaGetSymbolAddress((void**)&Uf,  g_U);
    cudaGetSymbolAddress((void**)&AOf, g_AO);
    cudaGetSymbolAddress((void**)&Of,  g_O);
    cudaGetSymbolAddress((void**)&X12, g_X12);
    cudaGetSymbolAddress((void**)&A1h, g_A1h);
    cudaGetSymbolAddress((void**)&A1l, g_A1l);
    cudaGetSymbolAddress((void**)&A2h, g_A2h);
    cudaGetSymbolAddress((void**)&A2l, g_A2l);
    cudaGetSymbolAddress((void**)&WTh, g_WTh);
    cudaGetSymbolAddress((void**)&WTl, g_WTl);

    const size_t NEL = (size_t)M_ROWS * D_MODEL;   // 4M
    __nv_bfloat16 *Qhb = (__nv_bfloat16*)Qf,  *Qlb = Qhb + NEL;
    __nv_bfloat16 *Khb = (__nv_bfloat16*)Kf,  *Klb = Khb + NEL;
    __nv_bfloat16 *VTh = (__nv_bfloat16*)Vf,  *VTl = VTh + NEL;

    const size_t W1M = (size_t)1024*1024;
    __nv_bfloat16 *Tq_h = WTh + 0*W1M, *Tq_l = WTl + 0*W1M;
    __nv_bfloat16 *Tk_h = WTh + 1*W1M, *Tk_l = WTl + 1*W1M;
    __nv_bfloat16 *Tv_h = WTh + 2*W1M, *Tv_l = WTl + 2*W1M;
    __nv_bfloat16 *Tu_h = WTh + 3*W1M, *Tu_l = WTl + 3*W1M;
    __nv_bfloat16 *T0_h = WTh + 4*W1M, *T0_l = WTl + 4*W1M;
    __nv_bfloat16 *T2_h = WTh + 5*W1M, *T2_l = WTl + 5*W1M;
    __nv_bfloat16 *T1_h = WTh + 6*W1M, *T1_l = WTl + 6*W1M;

    const int GSM = 2 * STAGE_B;
    cudaFuncSetAttribute(gemm_hmma<0>, cudaFuncAttributeMaxDynamicSharedMemorySize, GSM);
    cudaFuncSetAttribute(gemm_hmma<1>, cudaFuncAttributeMaxDynamicSharedMemorySize, GSM);
    cudaFuncSetAttribute(gemm_hmma<2>, cudaFuncAttributeMaxDynamicSharedMemorySize, GSM);
    cudaFuncSetAttribute(gemm_hmma<3>, cudaFuncAttributeMaxDynamicSharedMemorySize, GSM);
    cudaFuncSetAttribute(gemm_hmma<4>, cudaFuncAttributeMaxDynamicSharedMemorySize, GSM);
    cudaFuncSetAttribute(attn_tc, cudaFuncAttributeMaxDynamicSharedMemorySize, ATT_SMEM);

    dim3 tb(32, 8);
    dim3 tg(32, 32);
    dim3 tg1(64, 32);

    wtsplit_k<<<tg,  tb>>>(wq, Tq_h, Tq_l, 1024, 1024);
    wtsplit_k<<<tg,  tb>>>(wk, Tk_h, Tk_l, 1024, 1024);
    wtsplit_k<<<tg,  tb>>>(wv, Tv_h, Tv_l, 1024, 1024);
    wtsplit_k<<<tg,  tb>>>(wu, Tu_h, Tu_l, 1024, 1024);
    wtsplit_k<<<tg,  tb>>>(w0, T0_h, T0_l, 1024, 1024);
    wtsplit_k<<<tg,  tb>>>(w2, T2_h, T2_l, 1024, 1024);
    wtsplit_k<<<tg1, tb>>>(w1, T1_h, T1_l, 1024, 2048);

    dim3 gP(4, 32);
    dim3 gW1(8, 32);

    rmsnorm_tc<<<M_ROWS, 256>>>(x, g_ams, A1h, A1l);
    gemm_hmma<3><<<gP, 512, GSM>>>(A1h, A1l, Tq_h, Tq_l, bq,  nullptr, nullptr, Qhb, Qlb, M_ROWS, 1024, 1024);
    gemm_hmma<3><<<gP, 512, GSM>>>(A1h, A1l, Tk_h, Tk_l, bk_, nullptr, nullptr, Khb, Klb, M_ROWS, 1024, 1024);
    gemm_hmma<4><<<gP, 512, GSM>>>(A1h, A1l, Tv_h, Tv_l, bv,  nullptr, nullptr, VTh, VTl, M_ROWS, 1024, 1024);
    gemm_hmma<1><<<gP, 512, GSM>>>(A1h, A1l, Tu_h, Tu_l, bu,  nullptr, Uf, nullptr, nullptr, M_ROWS, 1024, 1024);
    attn_tc<<<dim3(SEQ/128, N_HEADS, BATCH), 256, ATT_SMEM>>>(Qhb, Qlb, Khb, Klb, VTh, VTl, pb, AOf);
    ams_tc<<<M_ROWS, 256>>>(AOf, g_ams, Uf, A2h, A2l);
    gemm_hmma<2><<<gP, 512, GSM>>>(A2h, A2l, T0_h, T0_l, b0, x, Of, nullptr, nullptr, M_ROWS, 1024, 1024);
    rmsnorm_tc<<<M_ROWS, 256>>>(Of, g_mffn, A1h, A1l);
    gemm_hmma<0><<<gW1, 512, GSM>>>(A1h, A1l, T1_h, T1_l, b1, nullptr, X12, nullptr, nullptr, M_ROWS, 2048, 1024);
    swiglu_tc<<<4096, 256>>>(X12, A2h, A2l);
    gemm_hmma<2><<<gP, 512, GSM>>>(A2h, A2l, T2_h, T2_l, b2, Of, out, nullptr, nullptr, M_ROWS, 1024, 1024);
}

// round 6
// speedup vs baseline: 2.0112x; 1.1592x over previous
#include <cuda_runtime.h>
#include <cuda_bf16.h>
#include <cstdint>
#include <math.h>

#define D_MODEL 1024
#define N_HEADS 16
#define DH      64
#define BATCH   2
#define SEQ     2048
#define M_ROWS  (BATCH*SEQ)   // 4096

// ---------------- scratch (static device globals; no allocations) ----------
__device__ float g_Q  [M_ROWS*D_MODEL];   // aliased: Qh/Ql bf16
__device__ float g_K  [M_ROWS*D_MODEL];   // aliased: Kh/Kl bf16
__device__ float g_V  [M_ROWS*D_MODEL];   // aliased: VTh/VTl bf16 (transposed per head)
__device__ float g_U  [M_ROWS*D_MODEL];
__device__ float g_AO [M_ROWS*D_MODEL];
__device__ float g_O  [M_ROWS*D_MODEL];
__device__ float g_X12[M_ROWS*2*D_MODEL];

__device__ __nv_bfloat16 g_A1h[M_ROWS*D_MODEL];
__device__ __nv_bfloat16 g_A1l[M_ROWS*D_MODEL];
__device__ __nv_bfloat16 g_A2h[M_ROWS*D_MODEL];
__device__ __nv_bfloat16 g_A2l[M_ROWS*D_MODEL];

__device__ __nv_bfloat16 g_WTh[8*1024*1024];
__device__ __nv_bfloat16 g_WTl[8*1024*1024];

__device__ __forceinline__ float siluf(float z) {
    return z * (1.0f / (1.0f + __expf(-z)));
}

__device__ __forceinline__ uint32_t smem_u32(const void* p) {
    uint32_t a;
    asm("{ .reg .u64 t; cvta.to.shared.u64 t, %1; cvt.u32.u64 %0, t; }" : "=r"(a) : "l"(p));
    return a;
}

__device__ __forceinline__ void ldsm_x4(uint32_t* r, uint32_t a) {
    asm volatile("ldmatrix.sync.aligned.m8n8.x4.shared.b16 {%0,%1,%2,%3}, [%4];"
                 : "=r"(r[0]), "=r"(r[1]), "=r"(r[2]), "=r"(r[3]) : "r"(a));
}

__device__ __forceinline__ void mma16816(float* c, const uint32_t* a, uint32_t b0, uint32_t b1) {
    asm volatile("mma.sync.aligned.m16n8k16.row.col.f32.bf16.bf16.f32 "
                 "{%0,%1,%2,%3}, {%4,%5,%6,%7}, {%8,%9}, {%0,%1,%2,%3};"
                 : "+f"(c[0]), "+f"(c[1]), "+f"(c[2]), "+f"(c[3])
                 : "r"(a[0]), "r"(a[1]), "r"(a[2]), "r"(a[3]), "r"(b0), "r"(b1));
}

__device__ __forceinline__ void cp16(uint32_t dst, const void* src) {
    asm volatile("cp.async.cg.shared.global [%0], [%1], 16;" :: "r"(dst), "l"(src));
}
__device__ __forceinline__ void cp_commit() { asm volatile("cp.async.commit_group;"); }
__device__ __forceinline__ void cp_wait1()  { asm volatile("cp.async.wait_group 1;"); }
__device__ __forceinline__ void cp_wait0()  { asm volatile("cp.async.wait_group 0;"); }

__device__ __forceinline__ void split_bf16(float v, __nv_bfloat16& h, __nv_bfloat16& l) {
    h = __float2bfloat16(v);
    l = __float2bfloat16(v - __bfloat162float(h));
}

// ============ weight transpose + bf16 split: W[K,N] -> T[N,K] hi/lo ========
__global__ void __launch_bounds__(256)
wtsplit_k(const float* __restrict__ W, __nv_bfloat16* __restrict__ Thi,
          __nv_bfloat16* __restrict__ Tlo, int K, int N)
{
    __shared__ float t[32][33];
    int tx = threadIdx.x, ty = threadIdx.y;
    int n0 = blockIdx.x * 32, k0 = blockIdx.y * 32;
    #pragma unroll
    for (int i = 0; i < 4; i++)
        t[ty + i*8][tx] = W[(size_t)(k0 + ty + i*8) * N + n0 + tx];
    __syncthreads();
    #pragma unroll
    for (int i = 0; i < 4; i++) {
        float v = t[tx][ty + i*8];
        __nv_bfloat16 hi, lo;
        split_bf16(v, hi, lo);
        size_t off = (size_t)(n0 + ty + i*8) * K + k0 + tx;
        Thi[off] = hi; Tlo[off] = lo;
    }
}

// ---------------- RMSNorm -> bf16 hi/lo -------------------------------------
__global__ void __launch_bounds__(256)
rmsnorm_tc(const float* __restrict__ X, const float* __restrict__ g,
           __nv_bfloat16* __restrict__ Yh, __nv_bfloat16* __restrict__ Yl)
{
    int r = blockIdx.x, t = threadIdx.x;
    float4 v = ((const float4*)(X + (size_t)r * D_MODEL))[t];
    float ss = v.x*v.x + v.y*v.y + v.z*v.z + v.w*v.w;
    #pragma unroll
    for (int o = 16; o; o >>= 1) ss += __shfl_xor_sync(0xffffffffu, ss, o);
    __shared__ float ws[8]; __shared__ float s_inv;
    if ((t & 31) == 0) ws[t >> 5] = ss;
    __syncthreads();
    if (t == 0) {
        float tot = 0.f;
        #pragma unroll
        for (int i = 0; i < 8; i++) tot += ws[i];
        s_inv = rsqrtf(tot * (1.0f / D_MODEL) + 1e-8f);
    }
    __syncthreads();
    float iv = s_inv;
    float4 gv = ((const float4*)g)[t];
    float o[4] = {v.x*iv*gv.x, v.y*iv*gv.y, v.z*iv*gv.z, v.w*iv*gv.w};
    __nv_bfloat16 h[4], l[4];
    #pragma unroll
    for (int i = 0; i < 4; i++) split_bf16(o[i], h[i], l[i]);
    size_t base = (size_t)r * D_MODEL + t*4;
    *(__nv_bfloat162*)(Yh + base)     = __nv_bfloat162(h[0], h[1]);
    *(__nv_bfloat162*)(Yh + base + 2) = __nv_bfloat162(h[2], h[3]);
    *(__nv_bfloat162*)(Yl + base)     = __nv_bfloat162(l[0], l[1]);
    *(__nv_bfloat162*)(Yl + base + 2) = __nv_bfloat162(l[2], l[3]);
}

// -------- ams: out = rmsnorm(A, g) * U -> bf16 hi/lo ------------------------
__global__ void __launch_bounds__(256)
ams_tc(const float* __restrict__ A, const float* __restrict__ g,
       const float* __restrict__ U,
       __nv_bfloat16* __restrict__ Yh, __nv_bfloat16* __restrict__ Yl)
{
    int r = blockIdx.x, t = threadIdx.x;
    float4 v = ((const float4*)(A + (size_t)r * D_MODEL))[t];
    float ss = v.x*v.x + v.y*v.y + v.z*v.z + v.w*v.w;
    #pragma unroll
    for (int o = 16; o; o >>= 1) ss += __shfl_xor_sync(0xffffffffu, ss, o);
    __shared__ float ws[8]; __shared__ float s_inv;
    if ((t & 31) == 0) ws[t >> 5] = ss;
    __syncthreads();
    if (t == 0) {
        float tot = 0.f;
        #pragma unroll
        for (int i = 0; i < 8; i++) tot += ws[i];
        s_inv = rsqrtf(tot * (1.0f / D_MODEL) + 1e-8f);
    }
    __syncthreads();
    float iv = s_inv;
    float4 gv = ((const float4*)g)[t];
    float4 uv = ((const float4*)(U + (size_t)r * D_MODEL))[t];
    float o[4] = {v.x*iv*gv.x*uv.x, v.y*iv*gv.y*uv.y, v.z*iv*gv.z*uv.z, v.w*iv*gv.w*uv.w};
    __nv_bfloat16 h[4], l[4];
    #pragma unroll
    for (int i = 0; i < 4; i++) split_bf16(o[i], h[i], l[i]);
    size_t base = (size_t)r * D_MODEL + t*4;
    *(__nv_bfloat162*)(Yh + base)     = __nv_bfloat162(h[0], h[1]);
    *(__nv_bfloat162*)(Yh + base + 2) = __nv_bfloat162(h[2], h[3]);
    *(__nv_bfloat162*)(Yl + base)     = __nv_bfloat162(l[0], l[1]);
    *(__nv_bfloat162*)(Yl + base + 2) = __nv_bfloat162(l[2], l[3]);
}

// -------- swiglu -> bf16 hi/lo ----------------------------------------------
__global__ void __launch_bounds__(256)
swiglu_tc(const float* __restrict__ X12,
          __nv_bfloat16* __restrict__ Yh, __nv_bfloat16* __restrict__ Yl)
{
    int i4 = blockIdx.x * blockDim.x + threadIdx.x;
    int r  = i4 >> 8;
    int c4 = i4 & 255;
    float4 a = ((const float4*)(X12 + (size_t)r * 2048))[c4];
    float4 b = ((const float4*)(X12 + (size_t)r * 2048 + 1024))[c4];
    float o[4] = {siluf(a.x)*b.x, siluf(a.y)*b.y, siluf(a.z)*b.z, siluf(a.w)*b.w};
    __nv_bfloat16 h[4], l[4];
    #pragma unroll
    for (int i = 0; i < 4; i++) split_bf16(o[i], h[i], l[i]);
    size_t base = (size_t)r * 1024 + c4*4;
    *(__nv_bfloat162*)(Yh + base)     = __nv_bfloat162(h[0], h[1]);
    *(__nv_bfloat162*)(Yh + base + 2) = __nv_bfloat162(h[2], h[3]);
    *(__nv_bfloat162*)(Yl + base)     = __nv_bfloat162(l[0], l[1]);
    *(__nv_bfloat162*)(Yl + base + 2) = __nv_bfloat162(l[2], l[3]);
}

// ============== HMMA GEMM: C = (Ah+Al)[M,K] @ (Bh+Bl)[N,K]^T + bias =========
// EPI: 0 bias->f32, 1 silu->f32, 2 bias+R->f32, 3 bias->bf16 hi/lo,
//      4 bias->bf16 hi/lo transposed per head (VT[b,h][d][t])
#define SM_A_HI 0
#define SM_A_LO 16384
#define SM_B_HI 32768
#define SM_B_LO 65536
#define STAGE_B 98304

template<int EPI>
__global__ void __launch_bounds__(512, 1)
gemm_hmma(const __nv_bfloat16* __restrict__ Ah, const __nv_bfloat16* __restrict__ Al,
          const __nv_bfloat16* __restrict__ Bh, const __nv_bfloat16* __restrict__ Bl,
          const float* __restrict__ bias, const float* __restrict__ R,
          float* __restrict__ C, __nv_bfloat16* __restrict__ Yh,
          __nv_bfloat16* __restrict__ Yl, int M, int N, int K)
{
    extern __shared__ __align__(128) char sm[];
    uint32_t sb = smem_u32(sm);
    int tid  = threadIdx.x;
    int wid  = tid >> 5;
    int lane = tid & 31;
    int wm = wid & 1, wn = wid >> 1;
    int bm = blockIdx.y * 128, bn = blockIdx.x * 256;
    int m0 = wm * 64, n0 = wn * 32;

    int laneRow = lane & 15;
    int laneK   = (lane >> 4) * 16;
    uint32_t xorA = (uint32_t)((laneRow & 7) << 4);

    float acc[4][4][4];
    #pragma unroll
    for (int i = 0; i < 4; i++)
        #pragma unroll
        for (int j = 0; j < 4; j++)
            #pragma unroll
            for (int q = 0; q < 4; q++) acc[i][j][q] = 0.f;

    const int NCH = K >> 6;

    auto load_stage = [&](int s, int chunk) {
        uint32_t st = sb + s * STAGE_B;
        int k0 = chunk * 64;
        #pragma unroll
        for (int it = 0; it < 2; it++) {
            int idx = tid + it * 512;
            int row = idx >> 3, c = idx & 7;
            uint32_t d = st + row * 128 + (uint32_t)((c * 16) ^ ((row & 7) << 4));
            size_t go = (size_t)(bm + row) * K + k0 + c * 8;
            cp16(d + SM_A_HI, Ah + go);
            cp16(d + SM_A_LO, Al + go);
        }
        #pragma unroll
        for (int it = 0; it < 4; it++) {
            int idx = tid + it * 512;
            int row = idx >> 3, c = idx & 7;
            uint32_t d = st + row * 128 + (uint32_t)((c * 16) ^ ((row & 7) << 4));
            size_t go = (size_t)(bn + row) * K + k0 + c * 8;
            cp16(d + SM_B_HI, Bh + go);
            cp16(d + SM_B_LO, Bl + go);
        }
    };

    load_stage(0, 0);
    cp_commit();

    for (int chunk = 0; chunk < NCH; chunk++) {
        int s = chunk & 1;
        if (chunk + 1 < NCH) {
            load_stage(s ^ 1, chunk + 1);
            cp_commit();
            cp_wait1();
        } else {
            cp_wait0();
        }
        __syncthreads();

        uint32_t st = sb + s * STAGE_B;
        // fragment-reuse 3-pass: hh, lh (reuse Bh), hl (reuse Ah)
        #pragma unroll
        for (int ks = 0; ks < 4; ks++) {
            uint32_t kb = (uint32_t)((ks * 32 + laneK) ^ xorA);
            uint32_t ah[4][4], bh[2][4];
            #pragma unroll
            for (int i = 0; i < 4; i++)
                ldsm_x4(ah[i], st + SM_A_HI + (uint32_t)(m0 + i*16 + laneRow) * 128 + kb);
            #pragma unroll
            for (int p = 0; p < 2; p++)
                ldsm_x4(bh[p], st + SM_B_HI + (uint32_t)(n0 + p*16 + laneRow) * 128 + kb);
            #pragma unroll
            for (int i = 0; i < 4; i++)
                #pragma unroll
                for (int j = 0; j < 4; j++)
                    mma16816(acc[i][j], ah[i], bh[j>>1][j&1], bh[j>>1][2 + (j&1)]);
            {
                uint32_t al[4][4];
                #pragma unroll
                for (int i = 0; i < 4; i++)
                    ldsm_x4(al[i], st + SM_A_LO + (uint32_t)(m0 + i*16 + laneRow) * 128 + kb);
                #pragma unroll
                for (int i = 0; i < 4; i++)
                    #pragma unroll
                    for (int j = 0; j < 4; j++)
                        mma16816(acc[i][j], al[i], bh[j>>1][j&1], bh[j>>1][2 + (j&1)]);
            }
            {
                uint32_t bl[2][4];
                #pragma unroll
                for (int p = 0; p < 2; p++)
                    ldsm_x4(bl[p], st + SM_B_LO + (uint32_t)(n0 + p*16 + laneRow) * 128 + kb);
                #pragma unroll
                for (int i = 0; i < 4; i++)
                    #pragma unroll
                    for (int j = 0; j < 4; j++)
                        mma16816(acc[i][j], ah[i], bl[j>>1][j&1], bl[j>>1][2 + (j&1)]);
            }
        }
        __syncthreads();
    }

    // ---- epilogue ----
    int group = lane >> 2, tq = lane & 3;
    #pragma unroll
    for (int j = 0; j < 4; j++) {
        int n = bn + n0 + j*8 + tq*2;
        float bv0 = bias[n], bv1 = bias[n+1];
        #pragma unroll
        for (int i = 0; i < 4; i++) {
            int m = bm + m0 + i*16 + group;
            float v0 = acc[i][j][0] + bv0, v1 = acc[i][j][1] + bv1;
            float v2 = acc[i][j][2] + bv0, v3 = acc[i][j][3] + bv1;
            if (EPI == 1) { v0 = siluf(v0); v1 = siluf(v1); v2 = siluf(v2); v3 = siluf(v3); }
            if (EPI <= 2) {
                size_t off0 = (size_t)m * N + n;
                size_t off1 = (size_t)(m + 8) * N + n;
                if (EPI == 2) {
                    float2 r0 = *(const float2*)(R + off0);
                    float2 r1 = *(const float2*)(R + off1);
                    v0 += r0.x; v1 += r0.y; v2 += r1.x; v3 += r1.y;
                }
                *(float2*)(C + off0) = make_float2(v0, v1);
                *(float2*)(C + off1) = make_float2(v2, v3);
            } else if (EPI == 3) {
                __nv_bfloat16 h0,l0,h1,l1,h2,l2,h3,l3;
                split_bf16(v0,h0,l0); split_bf16(v1,h1,l1);
                split_bf16(v2,h2,l2); split_bf16(v3,h3,l3);
                size_t off0 = (size_t)m * N + n;
                size_t off1 = (size_t)(m + 8) * N + n;
                *(__nv_bfloat162*)(Yh + off0) = __nv_bfloat162(h0, h1);
                *(__nv_bfloat162*)(Yl + off0) = __nv_bfloat162(l0, l1);
                *(__nv_bfloat162*)(Yh + off1) = __nv_bfloat162(h2, h3);
                *(__nv_bfloat162*)(Yl + off1) = __nv_bfloat162(l2, l3);
            } else {  // EPI == 4: VT[b,h][d][t]
                __nv_bfloat16 h0,l0,h1,l1,h2,l2,h3,l3;
                split_bf16(v0,h0,l0); split_bf16(v1,h1,l1);
                split_bf16(v2,h2,l2); split_bf16(v3,h3,l3);
                int bi = m >> 11, tt = m & 2047;
                int hh = n >> 6,  dd = n & 63;
                size_t vb = ((size_t)((bi*16 + hh)*64 + dd)) * 2048 + tt;
                Yh[vb]          = h0;  Yl[vb]          = l0;
                Yh[vb + 2048]   = h1;  Yl[vb + 2048]   = l1;
                Yh[vb + 8]      = h2;  Yl[vb + 8]      = l2;
                Yh[vb + 2056]   = h3;  Yl[vb + 2056]   = l3;
            }
        }
    }
}

// ================= tensor-core fused SiLU-attention ==========================
#define A_SQH 0u
#define A_SQL 16384u
#define A_SK  32768u       // + s*32768 : KH, KL(+16384)
#define A_SVT 98304u       // + s*32768 : VTH, VTL(+16384)
#define A_SS  163840u      // SH, SL(+32768)
#define ATT_SMEM 229376

__global__ void __launch_bounds__(256, 1)
attn_tc(const __nv_bfloat16* __restrict__ Qh, const __nv_bfloat16* __restrict__ Ql,
        const __nv_bfloat16* __restrict__ Kh, const __nv_bfloat16* __restrict__ Kl,
        const __nv_bfloat16* __restrict__ VTh, const __nv_bfloat16* __restrict__ VTl,
        const float* __restrict__ PB, float* __restrict__ O)
{
    extern __shared__ __align__(128) char sm[];
    uint32_t sb = smem_u32(sm);
    int tid  = threadIdx.x;
    int wid  = tid >> 5;
    int lane = tid & 31;
    int wm = wid & 1, wn = wid >> 1;
    int qt = blockIdx.x, h = blockIdx.y, b = blockIdx.z;
    int m0 = wm * 64, nS0 = wn * 32, nO0 = wn * 16;

    int laneRow = lane & 15;
    int laneK   = (lane >> 4) * 16;
    uint32_t xorA = (uint32_t)((laneRow & 7) << 4);
    int group = lane >> 2, tq = lane & 3;

    auto load_q = [&]() {
        #pragma unroll
        for (int it = 0; it < 4; it++) {
            int idx = tid + it * 256;
            int row = idx >> 3, c = idx & 7;
            uint32_t d = row * 128 + (uint32_t)((c * 16) ^ ((row & 7) << 4));
            size_t go = ((size_t)(b*SEQ + qt*128 + row)) * D_MODEL + h*64 + c*8;
            cp16(sb + A_SQH + d, Qh + go);
            cp16(sb + A_SQL + d, Ql + go);
        }
    };
    auto load_kv = [&](int s, int kt) {
        uint32_t kbase = sb + A_SK + (uint32_t)s * 32768u;
        #pragma unroll
        for (int it = 0; it < 4; it++) {
            int idx = tid + it * 256;
            int row = idx >> 3, c = idx & 7;
            uint32_t d = row * 128 + (uint32_t)((c * 16) ^ ((row & 7) << 4));
            size_t go = ((size_t)(b*SEQ + kt*128 + row)) * D_MODEL + h*64 + c*8;
            cp16(kbase + d, Kh + go);
            cp16(kbase + 16384u + d, Kl + go);
        }
        uint32_t vbase = sb + A_SVT + (uint32_t)s * 32768u;
        #pragma unroll
        for (int it = 0; it < 4; it++) {
            int idx = tid + it * 256;
            int row = idx >> 4, c = idx & 15;
            uint32_t d = row * 256 + (uint32_t)((c * 16) ^ ((row & 7) << 4));
            size_t go = ((size_t)((b*16 + h)*64 + row)) * 2048 + kt*128 + c*8;
            cp16(vbase + d, VTh + go);
            cp16(vbase + 16384u + d, VTl + go);
        }
    };

    float accO[4][2][4];
    #pragma unroll
    for (int i = 0; i < 4; i++)
        #pragma unroll
        for (int j = 0; j < 2; j++)
            #pragma unroll
            for (int q = 0; q < 4; q++) accO[i][j][q] = 0.f;

    load_q();
    load_kv(0, 0);
    cp_commit();

    for (int kt = 0; kt < SEQ/128; kt++) {
        int s = kt & 1;
        if (kt + 1 < SEQ/128) {
            load_kv(s ^ 1, kt + 1);
            cp_commit();
            cp_wait1();
        } else {
            cp_wait0();
        }
        __syncthreads();

        // ---- S = Q @ K^T, fragment-reuse 3 passes ----
        float acc[4][4][4];
        #pragma unroll
        for (int i = 0; i < 4; i++)
            #pragma unroll
            for (int j = 0; j < 4; j++)
                #pragma unroll
                for (int q = 0; q < 4; q++) acc[i][j][q] = 0.f;

        uint32_t kst = sb + A_SK + (uint32_t)s * 32768u;
        #pragma unroll
        for (int ks = 0; ks < 4; ks++) {
            uint32_t kb = (uint32_t)((ks * 32 + laneK) ^ xorA);
            uint32_t qhv[4][4], khv[2][4];
            #pragma unroll
            for (int i = 0; i < 4; i++)
                ldsm_x4(qhv[i], sb + A_SQH + (uint32_t)(m0 + i*16 + laneRow) * 128 + kb);
            #pragma unroll
            for (int p = 0; p < 2; p++)
                ldsm_x4(khv[p], kst + (uint32_t)(nS0 + p*16 + laneRow) * 128 + kb);
            #pragma unroll
            for (int i = 0; i < 4; i++)
                #pragma unroll
                for (int j = 0; j < 4; j++)
                    mma16816(acc[i][j], qhv[i], khv[j>>1][j&1], khv[j>>1][2 + (j&1)]);
            {
                uint32_t qlv[4][4];
                #pragma unroll
                for (int i = 0; i < 4; i++)
                    ldsm_x4(qlv[i], sb + A_SQL + (uint32_t)(m0 + i*16 + laneRow) * 128 + kb);
                #pragma unroll
                for (int i = 0; i < 4; i++)
                    #pragma unroll
                    for (int j = 0; j < 4; j++)
                        mma16816(acc[i][j], qlv[i], khv[j>>1][j&1], khv[j>>1][2 + (j&1)]);
            }
            {
                uint32_t klv[2][4];
                #pragma unroll
                for (int p = 0; p < 2; p++)
                    ldsm_x4(klv[p], kst + 16384u + (uint32_t)(nS0 + p*16 + laneRow) * 128 + kb);
                #pragma unroll
                for (int i = 0; i < 4; i++)
                    #pragma unroll
                    for (int j = 0; j < 4; j++)
                        mma16816(acc[i][j], qhv[i], klv[j>>1][j&1], klv[j>>1][2 + (j&1)]);
            }
        }

        // ---- silu(scale*S + pb) -> Ssm hi/lo ----
        #pragma unroll
        for (int j = 0; j < 4; j++) {
            int tl = nS0 + j*8 + tq*2;
            int tg = kt*128 + tl;
            float pb0 = PB[(size_t)tg * N_HEADS + h];
            float pb1 = PB[(size_t)(tg + 1) * N_HEADS + h];
            uint32_t tb = (uint32_t)(tl * 2);
            #pragma unroll
            for (int i = 0; i < 4; i++) {
                int m = m0 + i*16 + group;
                float w0 = siluf(acc[i][j][0] * 0.125f + pb0);
                float w1 = siluf(acc[i][j][1] * 0.125f + pb1);
                float w2 = siluf(acc[i][j][2] * 0.125f + pb0);
                float w3 = siluf(acc[i][j][3] * 0.125f + pb1);
                __nv_bfloat16 h0,l0,h1,l1,h2,l2,h3,l3;
                split_bf16(w0,h0,l0); split_bf16(w1,h1,l1);
                split_bf16(w2,h2,l2); split_bf16(w3,h3,l3);
                uint32_t sw = tb ^ (uint32_t)((m & 7) << 4);
                uint32_t a0 = (uint32_t)m * 256 + sw;
                uint32_t a1 = (uint32_t)(m + 8) * 256 + sw;
                *(__nv_bfloat162*)(sm + A_SS + a0)          = __nv_bfloat162(h0, h1);
                *(__nv_bfloat162*)(sm + A_SS + a0 + 32768)  = __nv_bfloat162(l0, l1);
                *(__nv_bfloat162*)(sm + A_SS + a1)          = __nv_bfloat162(h2, h3);
                *(__nv_bfloat162*)(sm + A_SS + a1 + 32768)  = __nv_bfloat162(l2, l3);
            }
        }
        __syncthreads();

        // ---- O += S @ V, fragment-reuse 3 passes ----
        uint32_t vst = sb + A_SVT + (uint32_t)s * 32768u;
        #pragma unroll
        for (int ks = 0; ks < 8; ks++) {
            uint32_t kb = (uint32_t)((ks * 32 + laneK) ^ xorA);
            uint32_t shv[4][4], vhv[4];
            #pragma unroll
            for (int i = 0; i < 4; i++)
                ldsm_x4(shv[i], sb + A_SS + (uint32_t)(m0 + i*16 + laneRow) * 256 + kb);
            ldsm_x4(vhv, vst + (uint32_t)(nO0 + laneRow) * 256 + kb);
            #pragma unroll
            for (int i = 0; i < 4; i++)
                #pragma unroll
                for (int j = 0; j < 2; j++)
                    mma16816(accO[i][j], shv[i], vhv[j], vhv[2 + j]);
            {
                uint32_t slv[4][4];
                #pragma unroll
                for (int i = 0; i < 4; i++)
                    ldsm_x4(slv[i], sb + A_SS + 32768u + (uint32_t)(m0 + i*16 + laneRow) * 256 + kb);
                #pragma unroll
                for (int i = 0; i < 4; i++)
                    #pragma unroll
                    for (int j = 0; j < 2; j++)
                        mma16816(accO[i][j], slv[i], vhv[j], vhv[2 + j]);
            }
            {
                uint32_t vlv[4];
                ldsm_x4(vlv, vst + 16384u + (uint32_t)(nO0 + laneRow) * 256 + kb);
                #pragma unroll
                for (int i = 0; i < 4; i++)
                    #pragma unroll
                    for (int j = 0; j < 2; j++)
                        mma16816(accO[i][j], shv[i], vlv[j], vlv[2 + j]);
            }
        }
        __syncthreads();
    }

    // ---- write O ----
    #pragma unroll
    for (int j = 0; j < 2; j++) {
        int col = h*64 + nO0 + j*8 + tq*2;
        #pragma unroll
        for (int i = 0; i < 4; i++) {
            int row = b*SEQ + qt*128 + m0 + i*16 + group;
            *(float2*)(O + (size_t)row * D_MODEL + col) =
                make_float2(accO[i][j][0], accO[i][j][1]);
            *(float2*)(O + (size_t)(row + 8) * D_MODEL + col) =
                make_float2(accO[i][j][2], accO[i][j][3]);
        }
    }
}

// ---------------- launch ----------------------------------------------------
extern "C" void kernel_launch(void* const* d_in, const int* in_sizes, int n_in,
                              void* d_out, int out_size)
{
    const float* x      = (const float*)d_in[0];
    const float* pb     = (const float*)d_in[2];
    const float* wq     = (const float*)d_in[3];
    const float* bq     = (const float*)d_in[4];
    const float* wk     = (const float*)d_in[5];
    const float* bk_    = (const float*)d_in[6];
    const float* wv     = (const float*)d_in[7];
    const float* bv     = (const float*)d_in[8];
    const float* wu     = (const float*)d_in[9];
    const float* bu     = (const float*)d_in[10];
    const float* g_ams  = (const float*)d_in[11];
    const float* w0     = (const float*)d_in[12];
    const float* b0     = (const float*)d_in[13];
    const float* w1     = (const float*)d_in[14];
    const float* b1     = (const float*)d_in[15];
    const float* w2     = (const float*)d_in[16];
    const float* b2     = (const float*)d_in[17];
    const float* g_mffn = (const float*)d_in[18];
    float* out = (float*)d_out;

    float *Qf, *Kf, *Vf, *Uf, *AOf, *Of, *X12;
    __nv_bfloat16 *A1h, *A1l, *A2h, *A2l, *WTh, *WTl;
    cudaGetSymbolAddress((void**)&Qf,  g_Q);
    cudaGetSymbolAddress((void**)&Kf,  g_K);
    cudaGetSymbolAddress((void**)&Vf,  g_V);
    cudaGetSymbolAddress((void**)&Uf,  g_U);
    cudaGetSymbolAddress((void**)&AOf, g_AO);
    cudaGetSymbolAddress((void**)&Of,  g_O);
    cudaGetSymbolAddress((void**)&X12, g_X12);
    cudaGetSymbolAddress((void**)&A1h, g_A1h);
    cudaGetSymbolAddress((void**)&A1l, g_A1l);
    cudaGetSymbolAddress((void**)&A2h, g_A2h);
    cudaGetSymbolAddress((void**)&A2l, g_A2l);
    cudaGetSymbolAddress((void**)&WTh, g_WTh);
    cudaGetSymbolAddress((void**)&WTl, g_WTl);

    const size_t NEL = (size_t)M_ROWS * D_MODEL;
    __nv_bfloat16 *Qhb = (__nv_bfloat16*)Qf,  *Qlb = Qhb + NEL;
    __nv_bfloat16 *Khb = (__nv_bfloat16*)Kf,  *Klb = Khb + NEL;
    __nv_bfloat16 *VTh = (__nv_bfloat16*)Vf,  *VTl = VTh + NEL;

    const size_t W1M = (size_t)1024*1024;
    __nv_bfloat16 *Tq_h = WTh + 0*W1M, *Tq_l = WTl + 0*W1M;
    __nv_bfloat16 *Tk_h = WTh + 1*W1M, *Tk_l = WTl + 1*W1M;
    __nv_bfloat16 *Tv_h = WTh + 2*W1M, *Tv_l = WTl + 2*W1M;
    __nv_bfloat16 *Tu_h = WTh + 3*W1M, *Tu_l = WTl + 3*W1M;
    __nv_bfloat16 *T0_h = WTh + 4*W1M, *T0_l = WTl + 4*W1M;
    __nv_bfloat16 *T2_h = WTh + 5*W1M, *T2_l = WTl + 5*W1M;
    __nv_bfloat16 *T1_h = WTh + 6*W1M, *T1_l = WTl + 6*W1M;

    const int GSM = 2 * STAGE_B;
    cudaFuncSetAttribute(gemm_hmma<0>, cudaFuncAttributeMaxDynamicSharedMemorySize, GSM);
    cudaFuncSetAttribute(gemm_hmma<1>, cudaFuncAttributeMaxDynamicSharedMemorySize, GSM);
    cudaFuncSetAttribute(gemm_hmma<2>, cudaFuncAttributeMaxDynamicSharedMemorySize, GSM);
    cudaFuncSetAttribute(gemm_hmma<3>, cudaFuncAttributeMaxDynamicSharedMemorySize, GSM);
    cudaFuncSetAttribute(gemm_hmma<4>, cudaFuncAttributeMaxDynamicSharedMemorySize, GSM);
    cudaFuncSetAttribute(attn_tc, cudaFuncAttributeMaxDynamicSharedMemorySize, ATT_SMEM);

    dim3 tb(32, 8);
    dim3 tg(32, 32);
    dim3 tg1(64, 32);

    wtsplit_k<<<tg,  tb>>>(wq, Tq_h, Tq_l, 1024, 1024);
    wtsplit_k<<<tg,  tb>>>(wk, Tk_h, Tk_l, 1024, 1024);
    wtsplit_k<<<tg,  tb>>>(wv, Tv_h, Tv_l, 1024, 1024);
    wtsplit_k<<<tg,  tb>>>(wu, Tu_h, Tu_l, 1024, 1024);
    wtsplit_k<<<tg,  tb>>>(w0, T0_h, T0_l, 1024, 1024);
    wtsplit_k<<<tg,  tb>>>(w2, T2_h, T2_l, 1024, 1024);
    wtsplit_k<<<tg1, tb>>>(w1, T1_h, T1_l, 1024, 2048);

    dim3 gP(4, 32);
    dim3 gW1(8, 32);

    rmsnorm_tc<<<M_ROWS, 256>>>(x, g_ams, A1h, A1l);
    gemm_hmma<3><<<gP, 512, GSM>>>(A1h, A1l, Tq_h, Tq_l, bq,  nullptr, nullptr, Qhb, Qlb, M_ROWS, 1024, 1024);
    gemm_hmma<3><<<gP, 512, GSM>>>(A1h, A1l, Tk_h, Tk_l, bk_, nullptr, nullptr, Khb, Klb, M_ROWS, 1024, 1024);
    gemm_hmma<4><<<gP, 512, GSM>>>(A1h, A1l, Tv_h, Tv_l, bv,  nullptr, nullptr, VTh, VTl, M_ROWS, 1024, 1024);
    gemm_hmma<1><<<gP, 512, GSM>>>(A1h, A1l, Tu_h, Tu_l, bu,  nullptr, Uf, nullptr, nullptr, M_ROWS, 1024, 1024);
    attn_tc<<<dim3(SEQ/128, N_HEADS, BATCH), 256, ATT_SMEM>>>(Qhb, Qlb, Khb, Klb, VTh, VTl, pb, AOf);
    ams_tc<<<M_ROWS, 256>>>(AOf, g_ams, Uf, A2h, A2l);
    gemm_hmma<2><<<gP, 512, GSM>>>(A2h, A2l, T0_h, T0_l, b0, x, Of, nullptr, nullptr, M_ROWS, 1024, 1024);
    rmsnorm_tc<<<M_ROWS, 256>>>(Of, g_mffn, A1h, A1l);
    gemm_hmma<0><<<gW1, 512, GSM>>>(A1h, A1l, T1_h, T1_l, b1, nullptr, X12, nullptr, nullptr, M_ROWS, 2048, 1024);
    swiglu_tc<<<4096, 256>>>(X12, A2h, A2l);
    gemm_hmma<2><<<gP, 512, GSM>>>(A2h, A2l, T2_h, T2_l, b2, Of, out, nullptr, nullptr, M_ROWS, 1024, 1024);
}

// round 7
// speedup vs baseline: 2.0649x; 1.0267x over previous
#include <cuda_runtime.h>
#include <cuda_bf16.h>
#include <cstdint>
#include <math.h>

#define D_MODEL 1024
#define N_HEADS 16
#define DH      64
#define BATCH   2
#define SEQ     2048
#define M_ROWS  (BATCH*SEQ)   // 4096

// ---------------- scratch (static device globals; no allocations) ----------
__device__ float g_Q  [M_ROWS*D_MODEL];   // aliased: Qh/Ql bf16
__device__ float g_K  [M_ROWS*D_MODEL];   // aliased: Kh/Kl bf16
__device__ float g_V  [M_ROWS*D_MODEL];   // aliased: VTh/VTl bf16 (transposed per head)
__device__ float g_U  [M_ROWS*D_MODEL];
__device__ float g_AO [M_ROWS*D_MODEL];
__device__ float g_O  [M_ROWS*D_MODEL];

__device__ __nv_bfloat16 g_A1h[M_ROWS*D_MODEL];
__device__ __nv_bfloat16 g_A1l[M_ROWS*D_MODEL];
__device__ __nv_bfloat16 g_A2h[M_ROWS*D_MODEL];
__device__ __nv_bfloat16 g_A2l[M_ROWS*D_MODEL];

__device__ __nv_bfloat16 g_WTh[8*1024*1024];
__device__ __nv_bfloat16 g_WTl[8*1024*1024];

#define W1M (1024*1024)

__device__ __forceinline__ float siluf(float z) {
    return z * (1.0f / (1.0f + __expf(-z)));
}

__device__ __forceinline__ uint32_t smem_u32(const void* p) {
    uint32_t a;
    asm("{ .reg .u64 t; cvta.to.shared.u64 t, %1; cvt.u32.u64 %0, t; }" : "=r"(a) : "l"(p));
    return a;
}

__device__ __forceinline__ void ldsm_x4(uint32_t* r, uint32_t a) {
    asm volatile("ldmatrix.sync.aligned.m8n8.x4.shared.b16 {%0,%1,%2,%3}, [%4];"
                 : "=r"(r[0]), "=r"(r[1]), "=r"(r[2]), "=r"(r[3]) : "r"(a));
}

__device__ __forceinline__ void mma16816(float* c, const uint32_t* a, uint32_t b0, uint32_t b1) {
    asm volatile("mma.sync.aligned.m16n8k16.row.col.f32.bf16.bf16.f32 "
                 "{%0,%1,%2,%3}, {%4,%5,%6,%7}, {%8,%9}, {%0,%1,%2,%3};"
                 : "+f"(c[0]), "+f"(c[1]), "+f"(c[2]), "+f"(c[3])
                 : "r"(a[0]), "r"(a[1]), "r"(a[2]), "r"(a[3]), "r"(b0), "r"(b1));
}

__device__ __forceinline__ void cp16(uint32_t dst, const void* src) {
    asm volatile("cp.async.cg.shared.global [%0], [%1], 16;" :: "r"(dst), "l"(src));
}
__device__ __forceinline__ void cp_commit() { asm volatile("cp.async.commit_group;"); }
__device__ __forceinline__ void cp_wait1()  { asm volatile("cp.async.wait_group 1;"); }
__device__ __forceinline__ void cp_wait0()  { asm volatile("cp.async.wait_group 0;"); }

__device__ __forceinline__ void split_bf16(float v, __nv_bfloat16& h, __nv_bfloat16& l) {
    h = __float2bfloat16(v);
    l = __float2bfloat16(v - __bfloat162float(h));
}

// ======= batched weight transpose + bf16 split (all 7 weights, 1 launch) ====
__global__ void __launch_bounds__(256)
wtsplit_all(const float* __restrict__ wq, const float* __restrict__ wk,
            const float* __restrict__ wv, const float* __restrict__ wu,
            const float* __restrict__ w0, const float* __restrict__ w2,
            const float* __restrict__ w1,
            __nv_bfloat16* __restrict__ WTh, __nv_bfloat16* __restrict__ WTl)
{
    __shared__ float t[32][33];
    int bid = blockIdx.x;
    const float* W; __nv_bfloat16 *Th, *Tl;
    int N, nx, ky;
    if (bid < 6144) {
        int w = bid >> 10, local = bid & 1023;
        switch (w) {
            case 0: W = wq; break; case 1: W = wk; break;
            case 2: W = wv; break; case 3: W = wu; break;
            case 4: W = w0; break; default: W = w2; break;
        }
        Th = WTh + (size_t)w * W1M; Tl = WTl + (size_t)w * W1M;
        N = 1024; nx = local & 31; ky = local >> 5;
    } else {
        int local = bid - 6144;
        W = w1; Th = WTh + (size_t)6 * W1M; Tl = WTl + (size_t)6 * W1M;
        N = 2048; nx = local & 63; ky = local >> 6;
    }
    const int K = 1024;
    int tx = threadIdx.x, ty = threadIdx.y;
    int n0 = nx * 32, k0 = ky * 32;
    #pragma unroll
    for (int i = 0; i < 4; i++)
        t[ty + i*8][tx] = W[(size_t)(k0 + ty + i*8) * N + n0 + tx];
    __syncthreads();
    #pragma unroll
    for (int i = 0; i < 4; i++) {
        float v = t[tx][ty + i*8];
        __nv_bfloat16 hi, lo;
        split_bf16(v, hi, lo);
        size_t off = (size_t)(n0 + ty + i*8) * K + k0 + tx;
        Th[off] = hi; Tl[off] = lo;
    }
}

// ---------------- RMSNorm -> bf16 hi/lo -------------------------------------
__global__ void __launch_bounds__(256)
rmsnorm_tc(const float* __restrict__ X, const float* __restrict__ g,
           __nv_bfloat16* __restrict__ Yh, __nv_bfloat16* __restrict__ Yl)
{
    int r = blockIdx.x, t = threadIdx.x;
    float4 v = ((const float4*)(X + (size_t)r * D_MODEL))[t];
    float ss = v.x*v.x + v.y*v.y + v.z*v.z + v.w*v.w;
    #pragma unroll
    for (int o = 16; o; o >>= 1) ss += __shfl_xor_sync(0xffffffffu, ss, o);
    __shared__ float ws[8]; __shared__ float s_inv;
    if ((t & 31) == 0) ws[t >> 5] = ss;
    __syncthreads();
    if (t == 0) {
        float tot = 0.f;
        #pragma unroll
        for (int i = 0; i < 8; i++) tot += ws[i];
        s_inv = rsqrtf(tot * (1.0f / D_MODEL) + 1e-8f);
    }
    __syncthreads();
    float iv = s_inv;
    float4 gv = ((const float4*)g)[t];
    float o[4] = {v.x*iv*gv.x, v.y*iv*gv.y, v.z*iv*gv.z, v.w*iv*gv.w};
    __nv_bfloat16 h[4], l[4];
    #pragma unroll
    for (int i = 0; i < 4; i++) split_bf16(o[i], h[i], l[i]);
    size_t base = (size_t)r * D_MODEL + t*4;
    *(__nv_bfloat162*)(Yh + base)     = __nv_bfloat162(h[0], h[1]);
    *(__nv_bfloat162*)(Yh + base + 2) = __nv_bfloat162(h[2], h[3]);
    *(__nv_bfloat162*)(Yl + base)     = __nv_bfloat162(l[0], l[1]);
    *(__nv_bfloat162*)(Yl + base + 2) = __nv_bfloat162(l[2], l[3]);
}

// -------- ams: out = rmsnorm(A, g) * U -> bf16 hi/lo ------------------------
__global__ void __launch_bounds__(256)
ams_tc(const float* __restrict__ A, const float* __restrict__ g,
       const float* __restrict__ U,
       __nv_bfloat16* __restrict__ Yh, __nv_bfloat16* __restrict__ Yl)
{
    int r = blockIdx.x, t = threadIdx.x;
    float4 v = ((const float4*)(A + (size_t)r * D_MODEL))[t];
    float ss = v.x*v.x + v.y*v.y + v.z*v.z + v.w*v.w;
    #pragma unroll
    for (int o = 16; o; o >>= 1) ss += __shfl_xor_sync(0xffffffffu, ss, o);
    __shared__ float ws[8]; __shared__ float s_inv;
    if ((t & 31) == 0) ws[t >> 5] = ss;
    __syncthreads();
    if (t == 0) {
        float tot = 0.f;
        #pragma unroll
        for (int i = 0; i < 8; i++) tot += ws[i];
        s_inv = rsqrtf(tot * (1.0f / D_MODEL) + 1e-8f);
    }
    __syncthreads();
    float iv = s_inv;
    float4 gv = ((const float4*)g)[t];
    float4 uv = ((const float4*)(U + (size_t)r * D_MODEL))[t];
    float o[4] = {v.x*iv*gv.x*uv.x, v.y*iv*gv.y*uv.y, v.z*iv*gv.z*uv.z, v.w*iv*gv.w*uv.w};
    __nv_bfloat16 h[4], l[4];
    #pragma unroll
    for (int i = 0; i < 4; i++) split_bf16(o[i], h[i], l[i]);
    size_t base = (size_t)r * D_MODEL + t*4;
    *(__nv_bfloat162*)(Yh + base)     = __nv_bfloat162(h[0], h[1]);
    *(__nv_bfloat162*)(Yh + base + 2) = __nv_bfloat162(h[2], h[3]);
    *(__nv_bfloat162*)(Yl + base)     = __nv_bfloat162(l[0], l[1]);
    *(__nv_bfloat162*)(Yl + base + 2) = __nv_bfloat162(l[2], l[3]);
}

// ============== HMMA GEMM (EPI 2 only): C = A@B^T + bias + R ================
#define SM_A_HI 0
#define SM_A_LO 16384
#define SM_B_HI 32768
#define SM_B_LO 65536
#define STAGE_B 98304

__global__ void __launch_bounds__(512, 1)
gemm_res(const __nv_bfloat16* __restrict__ Ah, const __nv_bfloat16* __restrict__ Al,
         const __nv_bfloat16* __restrict__ Bh, const __nv_bfloat16* __restrict__ Bl,
         const float* __restrict__ bias, const float* __restrict__ R,
         float* __restrict__ C, int M, int N, int K)
{
    extern __shared__ __align__(128) char sm[];
    uint32_t sb = smem_u32(sm);
    int tid  = threadIdx.x;
    int wid  = tid >> 5;
    int lane = tid & 31;
    int wm = wid & 1, wn = wid >> 1;
    int bm = blockIdx.y * 128, bn = blockIdx.x * 256;
    int m0 = wm * 64, n0 = wn * 32;

    int laneRow = lane & 15;
    int laneK   = (lane >> 4) * 16;
    uint32_t xorA = (uint32_t)((laneRow & 7) << 4);

    float acc[4][4][4];
    #pragma unroll
    for (int i = 0; i < 4; i++)
        #pragma unroll
        for (int j = 0; j < 4; j++)
            #pragma unroll
            for (int q = 0; q < 4; q++) acc[i][j][q] = 0.f;

    const int NCH = K >> 6;

    auto load_stage = [&](int s, int chunk) {
        uint32_t st = sb + s * STAGE_B;
        int k0 = chunk * 64;
        #pragma unroll
        for (int it = 0; it < 2; it++) {
            int idx = tid + it * 512;
            int row = idx >> 3, c = idx & 7;
            uint32_t d = st + row * 128 + (uint32_t)((c * 16) ^ ((row & 7) << 4));
            size_t go = (size_t)(bm + row) * K + k0 + c * 8;
            cp16(d + SM_A_HI, Ah + go);
            cp16(d + SM_A_LO, Al + go);
        }
        #pragma unroll
        for (int it = 0; it < 4; it++) {
            int idx = tid + it * 512;
            int row = idx >> 3, c = idx & 7;
            uint32_t d = st + row * 128 + (uint32_t)((c * 16) ^ ((row & 7) << 4));
            size_t go = (size_t)(bn + row) * K + k0 + c * 8;
            cp16(d + SM_B_HI, Bh + go);
            cp16(d + SM_B_LO, Bl + go);
        }
    };

    load_stage(0, 0);
    cp_commit();

    for (int chunk = 0; chunk < NCH; chunk++) {
        int s = chunk & 1;
        if (chunk + 1 < NCH) {
            load_stage(s ^ 1, chunk + 1);
            cp_commit();
            cp_wait1();
        } else {
            cp_wait0();
        }
        __syncthreads();

        uint32_t st = sb + s * STAGE_B;
        #pragma unroll
        for (int ks = 0; ks < 4; ks++) {
            uint32_t kb = (uint32_t)((ks * 32 + laneK) ^ xorA);
            uint32_t ah[4][4], bh[2][4];
            #pragma unroll
            for (int i = 0; i < 4; i++)
                ldsm_x4(ah[i], st + SM_A_HI + (uint32_t)(m0 + i*16 + laneRow) * 128 + kb);
            #pragma unroll
            for (int p = 0; p < 2; p++)
                ldsm_x4(bh[p], st + SM_B_HI + (uint32_t)(n0 + p*16 + laneRow) * 128 + kb);
            #pragma unroll
            for (int i = 0; i < 4; i++)
                #pragma unroll
                for (int j = 0; j < 4; j++)
                    mma16816(acc[i][j], ah[i], bh[j>>1][j&1], bh[j>>1][2 + (j&1)]);
            {
                uint32_t al[4][4];
                #pragma unroll
                for (int i = 0; i < 4; i++)
                    ldsm_x4(al[i], st + SM_A_LO + (uint32_t)(m0 + i*16 + laneRow) * 128 + kb);
                #pragma unroll
                for (int i = 0; i < 4; i++)
                    #pragma unroll
                    for (int j = 0; j < 4; j++)
                        mma16816(acc[i][j], al[i], bh[j>>1][j&1], bh[j>>1][2 + (j&1)]);
            }
            {
                uint32_t bl[2][4];
                #pragma unroll
                for (int p = 0; p < 2; p++)
                    ldsm_x4(bl[p], st + SM_B_LO + (uint32_t)(n0 + p*16 + laneRow) * 128 + kb);
                #pragma unroll
                for (int i = 0; i < 4; i++)
                    #pragma unroll
                    for (int j = 0; j < 4; j++)
                        mma16816(acc[i][j], ah[i], bl[j>>1][j&1], bl[j>>1][2 + (j&1)]);
            }
        }
        __syncthreads();
    }

    int group = lane >> 2, tq = lane & 3;
    #pragma unroll
    for (int j = 0; j < 4; j++) {
        int n = bn + n0 + j*8 + tq*2;
        float bv0 = bias[n], bv1 = bias[n+1];
        #pragma unroll
        for (int i = 0; i < 4; i++) {
            int m = bm + m0 + i*16 + group;
            size_t off0 = (size_t)m * N + n;
            size_t off1 = (size_t)(m + 8) * N + n;
            float2 r0 = *(const float2*)(R + off0);
            float2 r1 = *(const float2*)(R + off1);
            *(float2*)(C + off0) = make_float2(acc[i][j][0] + bv0 + r0.x, acc[i][j][1] + bv1 + r0.y);
            *(float2*)(C + off1) = make_float2(acc[i][j][2] + bv0 + r1.x, acc[i][j][3] + bv1 + r1.y);
        }
    }
}

// ====== fused Q/K/V/U projection: one launch, grid.z selects weight ========
// z=0: Q -> bf16 hi/lo;  z=1: K -> bf16 hi/lo;  z=2: V -> VT[b,h][d][t];
// z=3: U -> silu -> f32
__global__ void __launch_bounds__(512, 1)
proj4(const __nv_bfloat16* __restrict__ Ah, const __nv_bfloat16* __restrict__ Al,
      const __nv_bfloat16* __restrict__ WThG, const __nv_bfloat16* __restrict__ WTlG,
      const float* __restrict__ bq, const float* __restrict__ bk,
      const float* __restrict__ bv, const float* __restrict__ bu,
      __nv_bfloat16* __restrict__ Qh, __nv_bfloat16* __restrict__ Ql,
      __nv_bfloat16* __restrict__ Kh, __nv_bfloat16* __restrict__ Kl,
      __nv_bfloat16* __restrict__ VTh, __nv_bfloat16* __restrict__ VTl,
      float* __restrict__ Uf)
{
    extern __shared__ __align__(128) char sm[];
    uint32_t sb = smem_u32(sm);
    int tid  = threadIdx.x;
    int wid  = tid >> 5;
    int lane = tid & 31;
    int wm = wid & 1, wn = wid >> 1;
    int z  = blockIdx.z;
    int bm = blockIdx.y * 128, bn = blockIdx.x * 256;
    int m0 = wm * 64, n0 = wn * 32;
    const int K = 1024, N = 1024;

    const __nv_bfloat16* Bh = WThG + (size_t)z * W1M;
    const __nv_bfloat16* Bl = WTlG + (size_t)z * W1M;
    const float* bias = (z == 0) ? bq : (z == 1) ? bk : (z == 2) ? bv : bu;

    int laneRow = lane & 15;
    int laneK   = (lane >> 4) * 16;
    uint32_t xorA = (uint32_t)((laneRow & 7) << 4);

    float acc[4][4][4];
    #pragma unroll
    for (int i = 0; i < 4; i++)
        #pragma unroll
        for (int j = 0; j < 4; j++)
            #pragma unroll
            for (int q = 0; q < 4; q++) acc[i][j][q] = 0.f;

    const int NCH = K >> 6;

    auto load_stage = [&](int s, int chunk) {
        uint32_t st = sb + s * STAGE_B;
        int k0 = chunk * 64;
        #pragma unroll
        for (int it = 0; it < 2; it++) {
            int idx = tid + it * 512;
            int row = idx >> 3, c = idx & 7;
            uint32_t d = st + row * 128 + (uint32_t)((c * 16) ^ ((row & 7) << 4));
            size_t go = (size_t)(bm + row) * K + k0 + c * 8;
            cp16(d + SM_A_HI, Ah + go);
            cp16(d + SM_A_LO, Al + go);
        }
        #pragma unroll
        for (int it = 0; it < 4; it++) {
            int idx = tid + it * 512;
            int row = idx >> 3, c = idx & 7;
            uint32_t d = st + row * 128 + (uint32_t)((c * 16) ^ ((row & 7) << 4));
            size_t go = (size_t)(bn + row) * K + k0 + c * 8;
            cp16(d + SM_B_HI, Bh + go);
            cp16(d + SM_B_LO, Bl + go);
        }
    };

    load_stage(0, 0);
    cp_commit();

    for (int chunk = 0; chunk < NCH; chunk++) {
        int s = chunk & 1;
        if (chunk + 1 < NCH) {
            load_stage(s ^ 1, chunk + 1);
            cp_commit();
            cp_wait1();
        } else {
            cp_wait0();
        }
        __syncthreads();

        uint32_t st = sb + s * STAGE_B;
        #pragma unroll
        for (int ks = 0; ks < 4; ks++) {
            uint32_t kb = (uint32_t)((ks * 32 + laneK) ^ xorA);
            uint32_t ah[4][4], bh[2][4];
            #pragma unroll
            for (int i = 0; i < 4; i++)
                ldsm_x4(ah[i], st + SM_A_HI + (uint32_t)(m0 + i*16 + laneRow) * 128 + kb);
            #pragma unroll
            for (int p = 0; p < 2; p++)
                ldsm_x4(bh[p], st + SM_B_HI + (uint32_t)(n0 + p*16 + laneRow) * 128 + kb);
            #pragma unroll
            for (int i = 0; i < 4; i++)
                #pragma unroll
                for (int j = 0; j < 4; j++)
                    mma16816(acc[i][j], ah[i], bh[j>>1][j&1], bh[j>>1][2 + (j&1)]);
            {
                uint32_t al[4][4];
                #pragma unroll
                for (int i = 0; i < 4; i++)
                    ldsm_x4(al[i], st + SM_A_LO + (uint32_t)(m0 + i*16 + laneRow) * 128 + kb);
                #pragma unroll
                for (int i = 0; i < 4; i++)
                    #pragma unroll
                    for (int j = 0; j < 4; j++)
                        mma16816(acc[i][j], al[i], bh[j>>1][j&1], bh[j>>1][2 + (j&1)]);
            }
            {
                uint32_t bl[2][4];
                #pragma unroll
                for (int p = 0; p < 2; p++)
                    ldsm_x4(bl[p], st + SM_B_LO + (uint32_t)(n0 + p*16 + laneRow) * 128 + kb);
                #pragma unroll
                for (int i = 0; i < 4; i++)
                    #pragma unroll
                    for (int j = 0; j < 4; j++)
                        mma16816(acc[i][j], ah[i], bl[j>>1][j&1], bl[j>>1][2 + (j&1)]);
            }
        }
        __syncthreads();
    }

    int group = lane >> 2, tq = lane & 3;
    __nv_bfloat16* Yh = (z == 0) ? Qh : Kh;
    __nv_bfloat16* Yl = (z == 0) ? Ql : Kl;
    #pragma unroll
    for (int j = 0; j < 4; j++) {
        int n = bn + n0 + j*8 + tq*2;
        float bv0 = bias[n], bv1 = bias[n+1];
        #pragma unroll
        for (int i = 0; i < 4; i++) {
            int m = bm + m0 + i*16 + group;
            float v0 = acc[i][j][0] + bv0, v1 = acc[i][j][1] + bv1;
            float v2 = acc[i][j][2] + bv0, v3 = acc[i][j][3] + bv1;
            if (z <= 1) {
                __nv_bfloat16 h0,l0,h1,l1,h2,l2,h3,l3;
                split_bf16(v0,h0,l0); split_bf16(v1,h1,l1);
                split_bf16(v2,h2,l2); split_bf16(v3,h3,l3);
                size_t off0 = (size_t)m * N + n;
                size_t off1 = (size_t)(m + 8) * N + n;
                *(__nv_bfloat162*)(Yh + off0) = __nv_bfloat162(h0, h1);
                *(__nv_bfloat162*)(Yl + off0) = __nv_bfloat162(l0, l1);
                *(__nv_bfloat162*)(Yh + off1) = __nv_bfloat162(h2, h3);
                *(__nv_bfloat162*)(Yl + off1) = __nv_bfloat162(l2, l3);
            } else if (z == 2) {
                __nv_bfloat16 h0,l0,h1,l1,h2,l2,h3,l3;
                split_bf16(v0,h0,l0); split_bf16(v1,h1,l1);
                split_bf16(v2,h2,l2); split_bf16(v3,h3,l3);
                int bi = m >> 11, tt = m & 2047;
                int hh = n >> 6,  dd = n & 63;
                size_t vb = ((size_t)((bi*16 + hh)*64 + dd)) * 2048 + tt;
                VTh[vb]        = h0;  VTl[vb]        = l0;
                VTh[vb + 2048] = h1;  VTl[vb + 2048] = l1;
                VTh[vb + 8]    = h2;  VTl[vb + 8]    = l2;
                VTh[vb + 2056] = h3;  VTl[vb + 2056] = l3;
            } else {
                size_t off0 = (size_t)m * N + n;
                size_t off1 = (size_t)(m + 8) * N + n;
                *(float2*)(Uf + off0) = make_float2(siluf(v0), siluf(v1));
                *(float2*)(Uf + off1) = make_float2(siluf(v2), siluf(v3));
            }
        }
    }
}

// ====== w1 GEMM + swiglu fusion: per-CTA 128x128 tiles of BOTH halves ======
// x1 = A@W1T[bn..bn+128], x2 = A@W1T[1024+bn..], Y = split(silu(x1)*x2)
#define W_A_HI  0
#define W_A_LO  16384
#define W_B1_HI 32768
#define W_B1_LO 49152
#define W_B2_HI 65536
#define W_B2_LO 81920
#define STAGE_W 98304

__global__ void __launch_bounds__(512, 1)
gemm_w1sg(const __nv_bfloat16* __restrict__ Ah, const __nv_bfloat16* __restrict__ Al,
          const __nv_bfloat16* __restrict__ Bh, const __nv_bfloat16* __restrict__ Bl,
          const float* __restrict__ b1,
          __nv_bfloat16* __restrict__ Yh, __nv_bfloat16* __restrict__ Yl)
{
    extern __shared__ __align__(128) char sm[];
    uint32_t sb = smem_u32(sm);
    int tid  = threadIdx.x;
    int wid  = tid >> 5;
    int lane = tid & 31;
    int wm = wid & 1, wn = wid >> 1;          // 2 x 8, warp tile 64 x 16
    int bm = blockIdx.y * 128, bn = blockIdx.x * 128;
    int m0 = wm * 64, n0 = wn * 16;
    const int K = 1024;

    int laneRow = lane & 15;
    int laneK   = (lane >> 4) * 16;
    uint32_t xorA = (uint32_t)((laneRow & 7) << 4);

    float acc1[4][2][4], acc2[4][2][4];
    #pragma unroll
    for (int i = 0; i < 4; i++)
        #pragma unroll
        for (int j = 0; j < 2; j++)
            #pragma unroll
            for (int q = 0; q < 4; q++) { acc1[i][j][q] = 0.f; acc2[i][j][q] = 0.f; }

    const int NCH = K >> 6;

    auto load_stage = [&](int s, int chunk) {
        uint32_t st = sb + s * STAGE_W;
        int k0 = chunk * 64;
        #pragma unroll
        for (int it = 0; it < 2; it++) {
            int idx = tid + it * 512;
            int row = idx >> 3, c = idx & 7;
            uint32_t d = st + row * 128 + (uint32_t)((c * 16) ^ ((row & 7) << 4));
            size_t goA  = (size_t)(bm + row) * K + k0 + c * 8;
            size_t goB1 = (size_t)(bn + row) * K + k0 + c * 8;
            size_t goB2 = (size_t)(1024 + bn + row) * K + k0 + c * 8;
            cp16(d + W_A_HI,  Ah + goA);
            cp16(d + W_A_LO,  Al + goA);
            cp16(d + W_B1_HI, Bh + goB1);
            cp16(d + W_B1_LO, Bl + goB1);
            cp16(d + W_B2_HI, Bh + goB2);
            cp16(d + W_B2_LO, Bl + goB2);
        }
    };

    load_stage(0, 0);
    cp_commit();

    for (int chunk = 0; chunk < NCH; chunk++) {
        int s = chunk & 1;
        if (chunk + 1 < NCH) {
            load_stage(s ^ 1, chunk + 1);
            cp_commit();
            cp_wait1();
        } else {
            cp_wait0();
        }
        __syncthreads();

        uint32_t st = sb + s * STAGE_W;
        #pragma unroll
        for (int ks = 0; ks < 4; ks++) {
            uint32_t kb = (uint32_t)((ks * 32 + laneK) ^ xorA);
            uint32_t ah[4][4], b1h[4], b2h[4];
            #pragma unroll
            for (int i = 0; i < 4; i++)
                ldsm_x4(ah[i], st + W_A_HI + (uint32_t)(m0 + i*16 + laneRow) * 128 + kb);
            ldsm_x4(b1h, st + W_B1_HI + (uint32_t)(n0 + laneRow) * 128 + kb);
            ldsm_x4(b2h, st + W_B2_HI + (uint32_t)(n0 + laneRow) * 128 + kb);
            #pragma unroll
            for (int i = 0; i < 4; i++)
                #pragma unroll
                for (int j = 0; j < 2; j++) {
                    mma16816(acc1[i][j], ah[i], b1h[j], b1h[2 + j]);
                    mma16816(acc2[i][j], ah[i], b2h[j], b2h[2 + j]);
                }
            {
                uint32_t al[4][4];
                #pragma unroll
                for (int i = 0; i < 4; i++)
                    ldsm_x4(al[i], st + W_A_LO + (uint32_t)(m0 + i*16 + laneRow) * 128 + kb);
                #pragma unroll
                for (int i = 0; i < 4; i++)
                    #pragma unroll
                    for (int j = 0; j < 2; j++) {
                        mma16816(acc1[i][j], al[i], b1h[j], b1h[2 + j]);
                        mma16816(acc2[i][j], al[i], b2h[j], b2h[2 + j]);
                    }
            }
            {
                uint32_t b1l[4], b2l[4];
                ldsm_x4(b1l, st + W_B1_LO + (uint32_t)(n0 + laneRow) * 128 + kb);
                ldsm_x4(b2l, st + W_B2_LO + (uint32_t)(n0 + laneRow) * 128 + kb);
                #pragma unroll
                for (int i = 0; i < 4; i++)
                    #pragma unroll
                    for (int j = 0; j < 2; j++) {
                        mma16816(acc1[i][j], ah[i], b1l[j], b1l[2 + j]);
                        mma16816(acc2[i][j], ah[i], b2l[j], b2l[2 + j]);
                    }
            }
        }
        __syncthreads();
    }

    int group = lane >> 2, tq = lane & 3;
    #pragma unroll
    for (int j = 0; j < 2; j++) {
        int n = bn + n0 + j*8 + tq*2;
        float c10 = b1[n], c11 = b1[n+1];
        float c20 = b1[1024 + n], c21 = b1[1025 + n];
        #pragma unroll
        for (int i = 0; i < 4; i++) {
            int m = bm + m0 + i*16 + group;
            float y0 = siluf(acc1[i][j][0] + c10) * (acc2[i][j][0] + c20);
            float y1 = siluf(acc1[i][j][1] + c11) * (acc2[i][j][1] + c21);
            float y2 = siluf(acc1[i][j][2] + c10) * (acc2[i][j][2] + c20);
            float y3 = siluf(acc1[i][j][3] + c11) * (acc2[i][j][3] + c21);
            __nv_bfloat16 h0,l0,h1,l1,h2,l2,h3,l3;
            split_bf16(y0,h0,l0); split_bf16(y1,h1,l1);
            split_bf16(y2,h2,l2); split_bf16(y3,h3,l3);
            size_t off0 = (size_t)m * 1024 + n;
            size_t off1 = (size_t)(m + 8) * 1024 + n;
            *(__nv_bfloat162*)(Yh + off0) = __nv_bfloat162(h0, h1);
            *(__nv_bfloat162*)(Yl + off0) = __nv_bfloat162(l0, l1);
            *(__nv_bfloat162*)(Yh + off1) = __nv_bfloat162(h2, h3);
            *(__nv_bfloat162*)(Yl + off1) = __nv_bfloat162(l2, l3);
        }
    }
}

// ================= tensor-core fused SiLU-attention ==========================
#define A_SQH 0u
#define A_SQL 16384u
#define A_SK  32768u
#define A_SVT 98304u
#define A_SS  163840u
#define ATT_SMEM 229376

__global__ void __launch_bounds__(256, 1)
attn_tc(const __nv_bfloat16* __restrict__ Qh, const __nv_bfloat16* __restrict__ Ql,
        const __nv_bfloat16* __restrict__ Kh, const __nv_bfloat16* __restrict__ Kl,
        const __nv_bfloat16* __restrict__ VTh, const __nv_bfloat16* __restrict__ VTl,
        const float* __restrict__ PB, float* __restrict__ O)
{
    extern __shared__ __align__(128) char sm[];
    uint32_t sb = smem_u32(sm);
    int tid  = threadIdx.x;
    int wid  = tid >> 5;
    int lane = tid & 31;
    int wm = wid & 1, wn = wid >> 1;
    int qt = blockIdx.x, h = blockIdx.y, b = blockIdx.z;
    int m0 = wm * 64, nS0 = wn * 32, nO0 = wn * 16;

    int laneRow = lane & 15;
    int laneK   = (lane >> 4) * 16;
    uint32_t xorA = (uint32_t)((laneRow & 7) << 4);
    int group = lane >> 2, tq = lane & 3;

    auto load_q = [&]() {
        #pragma unroll
        for (int it = 0; it < 4; it++) {
            int idx = tid + it * 256;
            int row = idx >> 3, c = idx & 7;
            uint32_t d = row * 128 + (uint32_t)((c * 16) ^ ((row & 7) << 4));
            size_t go = ((size_t)(b*SEQ + qt*128 + row)) * D_MODEL + h*64 + c*8;
            cp16(sb + A_SQH + d, Qh + go);
            cp16(sb + A_SQL + d, Ql + go);
        }
    };
    auto load_kv = [&](int s, int kt) {
        uint32_t kbase = sb + A_SK + (uint32_t)s * 32768u;
        #pragma unroll
        for (int it = 0; it < 4; it++) {
            int idx = tid + it * 256;
            int row = idx >> 3, c = idx & 7;
            uint32_t d = row * 128 + (uint32_t)((c * 16) ^ ((row & 7) << 4));
            size_t go = ((size_t)(b*SEQ + kt*128 + row)) * D_MODEL + h*64 + c*8;
            cp16(kbase + d, Kh + go);
            cp16(kbase + 16384u + d, Kl + go);
        }
        uint32_t vbase = sb + A_SVT + (uint32_t)s * 32768u;
        #pragma unroll
        for (int it = 0; it < 4; it++) {
            int idx = tid + it * 256;
            int row = idx >> 4, c = idx & 15;
            uint32_t d = row * 256 + (uint32_t)((c * 16) ^ ((row & 7) << 4));
            size_t go = ((size_t)((b*16 + h)*64 + row)) * 2048 + kt*128 + c*8;
            cp16(vbase + d, VTh + go);
            cp16(vbase + 16384u + d, VTl + go);
        }
    };

    float accO[4][2][4];
    #pragma unroll
    for (int i = 0; i < 4; i++)
        #pragma unroll
        for (int j = 0; j < 2; j++)
            #pragma unroll
            for (int q = 0; q < 4; q++) accO[i][j][q] = 0.f;

    load_q();
    load_kv(0, 0);
    cp_commit();

    for (int kt = 0; kt < SEQ/128; kt++) {
        int s = kt & 1;
        if (kt + 1 < SEQ/128) {
            load_kv(s ^ 1, kt + 1);
            cp_commit();
            cp_wait1();
        } else {
            cp_wait0();
        }
        __syncthreads();

        float acc[4][4][4];
        #pragma unroll
        for (int i = 0; i < 4; i++)
            #pragma unroll
            for (int j = 0; j < 4; j++)
                #pragma unroll
                for (int q = 0; q < 4; q++) acc[i][j][q] = 0.f;

        uint32_t kst = sb + A_SK + (uint32_t)s * 32768u;
        #pragma unroll
        for (int ks = 0; ks < 4; ks++) {
            uint32_t kb = (uint32_t)((ks * 32 + laneK) ^ xorA);
            uint32_t qhv[4][4], khv[2][4];
            #pragma unroll
            for (int i = 0; i < 4; i++)
                ldsm_x4(qhv[i], sb + A_SQH + (uint32_t)(m0 + i*16 + laneRow) * 128 + kb);
            #pragma unroll
            for (int p = 0; p < 2; p++)
                ldsm_x4(khv[p], kst + (uint32_t)(nS0 + p*16 + laneRow) * 128 + kb);
            #pragma unroll
            for (int i = 0; i < 4; i++)
                #pragma unroll
                for (int j = 0; j < 4; j++)
                    mma16816(acc[i][j], qhv[i], khv[j>>1][j&1], khv[j>>1][2 + (j&1)]);
            {
                uint32_t qlv[4][4];
                #pragma unroll
                for (int i = 0; i < 4; i++)
                    ldsm_x4(qlv[i], sb + A_SQL + (uint32_t)(m0 + i*16 + laneRow) * 128 + kb);
                #pragma unroll
                for (int i = 0; i < 4; i++)
                    #pragma unroll
                    for (int j = 0; j < 4; j++)
                        mma16816(acc[i][j], qlv[i], khv[j>>1][j&1], khv[j>>1][2 + (j&1)]);
            }
            {
                uint32_t klv[2][4];
                #pragma unroll
                for (int p = 0; p < 2; p++)
                    ldsm_x4(klv[p], kst + 16384u + (uint32_t)(nS0 + p*16 + laneRow) * 128 + kb);
                #pragma unroll
                for (int i = 0; i < 4; i++)
                    #pragma unroll
                    for (int j = 0; j < 4; j++)
                        mma16816(acc[i][j], qhv[i], klv[j>>1][j&1], klv[j>>1][2 + (j&1)]);
            }
        }

        #pragma unroll
        for (int j = 0; j < 4; j++) {
            int tl = nS0 + j*8 + tq*2;
            int tg = kt*128 + tl;
            float pb0 = PB[(size_t)tg * N_HEADS + h];
            float pb1 = PB[(size_t)(tg + 1) * N_HEADS + h];
            uint32_t tb = (uint32_t)(tl * 2);
            #pragma unroll
            for (int i = 0; i < 4; i++) {
                int m = m0 + i*16 + group;
                float w0 = siluf(acc[i][j][0] * 0.125f + pb0);
                float w1 = siluf(acc[i][j][1] * 0.125f + pb1);
                float w2 = siluf(acc[i][j][2] * 0.125f + pb0);
                float w3 = siluf(acc[i][j][3] * 0.125f + pb1);
                __nv_bfloat16 h0,l0,h1,l1,h2,l2,h3,l3;
                split_bf16(w0,h0,l0); split_bf16(w1,h1,l1);
                split_bf16(w2,h2,l2); split_bf16(w3,h3,l3);
                uint32_t sw = tb ^ (uint32_t)((m & 7) << 4);
                uint32_t a0 = (uint32_t)m * 256 + sw;
                uint32_t a1 = (uint32_t)(m + 8) * 256 + sw;
                *(__nv_bfloat162*)(sm + A_SS + a0)          = __nv_bfloat162(h0, h1);
                *(__nv_bfloat162*)(sm + A_SS + a0 + 32768)  = __nv_bfloat162(l0, l1);
                *(__nv_bfloat162*)(sm + A_SS + a1)          = __nv_bfloat162(h2, h3);
                *(__nv_bfloat162*)(sm + A_SS + a1 + 32768)  = __nv_bfloat162(l2, l3);
            }
        }
        __syncthreads();

        uint32_t vst = sb + A_SVT + (uint32_t)s * 32768u;
        #pragma unroll
        for (int ks = 0; ks < 8; ks++) {
            uint32_t kb = (uint32_t)((ks * 32 + laneK) ^ xorA);
            uint32_t shv[4][4], vhv[4];
            #pragma unroll
            for (int i = 0; i < 4; i++)
                ldsm_x4(shv[i], sb + A_SS + (uint32_t)(m0 + i*16 + laneRow) * 256 + kb);
            ldsm_x4(vhv, vst + (uint32_t)(nO0 + laneRow) * 256 + kb);
            #pragma unroll
            for (int i = 0; i < 4; i++)
                #pragma unroll
                for (int j = 0; j < 2; j++)
                    mma16816(accO[i][j], shv[i], vhv[j], vhv[2 + j]);
            {
                uint32_t slv[4][4];
                #pragma unroll
                for (int i = 0; i < 4; i++)
                    ldsm_x4(slv[i], sb + A_SS + 32768u + (uint32_t)(m0 + i*16 + laneRow) * 256 + kb);
                #pragma unroll
                for (int i = 0; i < 4; i++)
                    #pragma unroll
                    for (int j = 0; j < 2; j++)
                        mma16816(accO[i][j], slv[i], vhv[j], vhv[2 + j]);
            }
            {
                uint32_t vlv[4];
                ldsm_x4(vlv, vst + 16384u + (uint32_t)(nO0 + laneRow) * 256 + kb);
                #pragma unroll
                for (int i = 0; i < 4; i++)
                    #pragma unroll
                    for (int j = 0; j < 2; j++)
                        mma16816(accO[i][j], shv[i], vlv[j], vlv[2 + j]);
            }
        }
        __syncthreads();
    }

    #pragma unroll
    for (int j = 0; j < 2; j++) {
        int col = h*64 + nO0 + j*8 + tq*2;
        #pragma unroll
        for (int i = 0; i < 4; i++) {
            int row = b*SEQ + qt*128 + m0 + i*16 + group;
            *(float2*)(O + (size_t)row * D_MODEL + col) =
                make_float2(accO[i][j][0], accO[i][j][1]);
            *(float2*)(O + (size_t)(row + 8) * D_MODEL + col) =
                make_float2(accO[i][j][2], accO[i][j][3]);
        }
    }
}

// ---------------- launch ----------------------------------------------------
extern "C" void kernel_launch(void* const* d_in, const int* in_sizes, int n_in,
                              void* d_out, int out_size)
{
    const float* x      = (const float*)d_in[0];
    const float* pb     = (const float*)d_in[2];
    const float* wq     = (const float*)d_in[3];
    const float* bq     = (const float*)d_in[4];
    const float* wk     = (const float*)d_in[5];
    const float* bk_    = (const float*)d_in[6];
    const float* wv     = (const float*)d_in[7];
    const float* bv     = (const float*)d_in[8];
    const float* wu     = (const float*)d_in[9];
    const float* bu     = (const float*)d_in[10];
    const float* g_ams  = (const float*)d_in[11];
    const float* w0     = (const float*)d_in[12];
    const float* b0     = (const float*)d_in[13];
    const float* w1     = (const float*)d_in[14];
    const float* b1     = (const float*)d_in[15];
    const float* w2     = (const float*)d_in[16];
    const float* b2     = (const float*)d_in[17];
    const float* g_mffn = (const float*)d_in[18];
    float* out = (float*)d_out;

    float *Qf, *Kf, *Vf, *Uf, *AOf, *Of;
    __nv_bfloat16 *A1h, *A1l, *A2h, *A2l, *WTh, *WTl;
    cudaGetSymbolAddress((void**)&Qf,  g_Q);
    cudaGetSymbolAddress((void**)&Kf,  g_K);
    cudaGetSymbolAddress((void**)&Vf,  g_V);
    cudaGetSymbolAddress((void**)&Uf,  g_U);
    cudaGetSymbolAddress((void**)&AOf, g_AO);
    cudaGetSymbolAddress((void**)&Of,  g_O);
    cudaGetSymbolAddress((void**)&A1h, g_A1h);
    cudaGetSymbolAddress((void**)&A1l, g_A1l);
    cudaGetSymbolAddress((void**)&A2h, g_A2h);
    cudaGetSymbolAddress((void**)&A2l, g_A2l);
    cudaGetSymbolAddress((void**)&WTh, g_WTh);
    cudaGetSymbolAddress((void**)&WTl, g_WTl);

    const size_t NEL = (size_t)M_ROWS * D_MODEL;
    __nv_bfloat16 *Qhb = (__nv_bfloat16*)Qf,  *Qlb = Qhb + NEL;
    __nv_bfloat16 *Khb = (__nv_bfloat16*)Kf,  *Klb = Khb + NEL;
    __nv_bfloat16 *VTh = (__nv_bfloat16*)Vf,  *VTl = VTh + NEL;

    __nv_bfloat16 *T0_h = WTh + (size_t)4*W1M, *T0_l = WTl + (size_t)4*W1M;
    __nv_bfloat16 *T2_h = WTh + (size_t)5*W1M, *T2_l = WTl + (size_t)5*W1M;
    __nv_bfloat16 *T1_h = WTh + (size_t)6*W1M, *T1_l = WTl + (size_t)6*W1M;

    const int GSM = 2 * STAGE_B;
    cudaFuncSetAttribute(gemm_res,  cudaFuncAttributeMaxDynamicSharedMemorySize, GSM);
    cudaFuncSetAttribute(proj4,     cudaFuncAttributeMaxDynamicSharedMemorySize, GSM);
    cudaFuncSetAttribute(gemm_w1sg, cudaFuncAttributeMaxDynamicSharedMemorySize, 2*STAGE_W);
    cudaFuncSetAttribute(attn_tc,   cudaFuncAttributeMaxDynamicSharedMemorySize, ATT_SMEM);

    // batched weight transpose + split (1 launch)
    wtsplit_all<<<8192, dim3(32, 8)>>>(wq, wk, wv, wu, w0, w2, w1, WTh, WTl);
    // x_norm -> bf16 hi/lo
    rmsnorm_tc<<<M_ROWS, 256>>>(x, g_ams, A1h, A1l);
    // fused Q/K/V/U projections (1 launch, 512 CTAs)
    proj4<<<dim3(4, 32, 4), 512, GSM>>>(A1h, A1l, WTh, WTl, bq, bk_, bv, bu,
                                        Qhb, Qlb, Khb, Klb, VTh, VTl, Uf);
    // fused silu-attention
    attn_tc<<<dim3(SEQ/128, N_HEADS, BATCH), 256, ATT_SMEM>>>(Qhb, Qlb, Khb, Klb, VTh, VTl, pb, AOf);
    // ams_out = rmsnorm(attn, g_ams) * u -> bf16
    ams_tc<<<M_ROWS, 256>>>(AOf, g_ams, Uf, A2h, A2l);
    // o = ams @ w0 + b0 + x
    gemm_res<<<dim3(4, 32), 512, GSM>>>(A2h, A2l, T0_h, T0_l, b0, x, Of, M_ROWS, 1024, 1024);
    // o_norm -> bf16
    rmsnorm_tc<<<M_ROWS, 256>>>(Of, g_mffn, A1h, A1l);
    // swiglu(o_norm @ w1 + b1) -> bf16 hi/lo  (fused)
    gemm_w1sg<<<dim3(8, 32), 512, 2*STAGE_W>>>(A1h, A1l, T1_h, T1_l, b1, A2h, A2l);
    // out = swiglu @ w2 + b2 + o
    gemm_res<<<dim3(4, 32), 512, GSM>>>(A2h, A2l, T2_h, T2_l, b2, Of, out, M_ROWS, 1024, 1024);
}

// round 8
// speedup vs baseline: 2.1228x; 1.0281x over previous
#include <cuda_runtime.h>
#include <cuda_bf16.h>
#include <cstdint>
#include <math.h>

#define D_MODEL 1024
#define N_HEADS 16
#define DH      64
#define BATCH   2
#define SEQ     2048
#define M_ROWS  (BATCH*SEQ)   // 4096

// ---------------- scratch (static device globals; no allocations) ----------
__device__ float g_Q  [M_ROWS*D_MODEL];   // aliased: Qh/Ql bf16
__device__ float g_K  [M_ROWS*D_MODEL];   // aliased: Kh/Kl bf16
__device__ float g_V  [M_ROWS*D_MODEL];   // aliased: VTh/VTl bf16 (transposed per head)
__device__ float g_U  [M_ROWS*D_MODEL];
__device__ float g_AO [M_ROWS*D_MODEL];
__device__ float g_O  [M_ROWS*D_MODEL];

__device__ __nv_bfloat16 g_A1h[M_ROWS*D_MODEL];
__device__ __nv_bfloat16 g_A1l[M_ROWS*D_MODEL];
__device__ __nv_bfloat16 g_A2h[M_ROWS*D_MODEL];
__device__ __nv_bfloat16 g_A2l[M_ROWS*D_MODEL];

__device__ __nv_bfloat16 g_WTh[8*1024*1024];
__device__ __nv_bfloat16 g_WTl[8*1024*1024];

#define W1M (1024*1024)

__device__ __forceinline__ float siluf(float z) {
    return z * (1.0f / (1.0f + __expf(-z)));
}

__device__ __forceinline__ uint32_t smem_u32(const void* p) {
    uint32_t a;
    asm("{ .reg .u64 t; cvta.to.shared.u64 t, %1; cvt.u32.u64 %0, t; }" : "=r"(a) : "l"(p));
    return a;
}

__device__ __forceinline__ void ldsm_x4(uint32_t* r, uint32_t a) {
    asm volatile("ldmatrix.sync.aligned.m8n8.x4.shared.b16 {%0,%1,%2,%3}, [%4];"
                 : "=r"(r[0]), "=r"(r[1]), "=r"(r[2]), "=r"(r[3]) : "r"(a));
}

__device__ __forceinline__ void mma16816(float* c, const uint32_t* a, uint32_t b0, uint32_t b1) {
    asm volatile("mma.sync.aligned.m16n8k16.row.col.f32.bf16.bf16.f32 "
                 "{%0,%1,%2,%3}, {%4,%5,%6,%7}, {%8,%9}, {%0,%1,%2,%3};"
                 : "+f"(c[0]), "+f"(c[1]), "+f"(c[2]), "+f"(c[3])
                 : "r"(a[0]), "r"(a[1]), "r"(a[2]), "r"(a[3]), "r"(b0), "r"(b1));
}

__device__ __forceinline__ void cp16(uint32_t dst, const void* src) {
    asm volatile("cp.async.cg.shared.global [%0], [%1], 16;" :: "r"(dst), "l"(src));
}
__device__ __forceinline__ void cp_commit() { asm volatile("cp.async.commit_group;"); }
__device__ __forceinline__ void cp_wait1()  { asm volatile("cp.async.wait_group 1;"); }
__device__ __forceinline__ void cp_wait0()  { asm volatile("cp.async.wait_group 0;"); }

__device__ __forceinline__ void split_bf16(float v, __nv_bfloat16& h, __nv_bfloat16& l) {
    h = __float2bfloat16(v);
    l = __float2bfloat16(v - __bfloat162float(h));
}

__device__ __forceinline__ uint32_t pack_bf16(__nv_bfloat16 a, __nv_bfloat16 b) {
    __nv_bfloat162 t(a, b);
    return *(uint32_t*)&t;
}

// ======= batched weight transpose + bf16 split (all 7 weights, 1 launch) ====
__global__ void __launch_bounds__(256)
wtsplit_all(const float* __restrict__ wq, const float* __restrict__ wk,
            const float* __restrict__ wv, const float* __restrict__ wu,
            const float* __restrict__ w0, const float* __restrict__ w2,
            const float* __restrict__ w1,
            __nv_bfloat16* __restrict__ WTh, __nv_bfloat16* __restrict__ WTl)
{
    __shared__ float t[32][33];
    int bid = blockIdx.x;
    const float* W; __nv_bfloat16 *Th, *Tl;
    int N, nx, ky;
    if (bid < 6144) {
        int w = bid >> 10, local = bid & 1023;
        switch (w) {
            case 0: W = wq; break; case 1: W = wk; break;
            case 2: W = wv; break; case 3: W = wu; break;
            case 4: W = w0; break; default: W = w2; break;
        }
        Th = WTh + (size_t)w * W1M; Tl = WTl + (size_t)w * W1M;
        N = 1024; nx = local & 31; ky = local >> 5;
    } else {
        int local = bid - 6144;
        W = w1; Th = WTh + (size_t)6 * W1M; Tl = WTl + (size_t)6 * W1M;
        N = 2048; nx = local & 63; ky = local >> 6;
    }
    const int K = 1024;
    int tx = threadIdx.x, ty = threadIdx.y;
    int n0 = nx * 32, k0 = ky * 32;
    #pragma unroll
    for (int i = 0; i < 4; i++)
        t[ty + i*8][tx] = W[(size_t)(k0 + ty + i*8) * N + n0 + tx];
    __syncthreads();
    #pragma unroll
    for (int i = 0; i < 4; i++) {
        float v = t[tx][ty + i*8];
        __nv_bfloat16 hi, lo;
        split_bf16(v, hi, lo);
        size_t off = (size_t)(n0 + ty + i*8) * K + k0 + tx;
        Th[off] = hi; Tl[off] = lo;
    }
}

// ---------------- RMSNorm -> bf16 hi/lo -------------------------------------
__global__ void __launch_bounds__(256)
rmsnorm_tc(const float* __restrict__ X, const float* __restrict__ g,
           __nv_bfloat16* __restrict__ Yh, __nv_bfloat16* __restrict__ Yl)
{
    int r = blockIdx.x, t = threadIdx.x;
    float4 v = ((const float4*)(X + (size_t)r * D_MODEL))[t];
    float ss = v.x*v.x + v.y*v.y + v.z*v.z + v.w*v.w;
    #pragma unroll
    for (int o = 16; o; o >>= 1) ss += __shfl_xor_sync(0xffffffffu, ss, o);
    __shared__ float ws[8]; __shared__ float s_inv;
    if ((t & 31) == 0) ws[t >> 5] = ss;
    __syncthreads();
    if (t == 0) {
        float tot = 0.f;
        #pragma unroll
        for (int i = 0; i < 8; i++) tot += ws[i];
        s_inv = rsqrtf(tot * (1.0f / D_MODEL) + 1e-8f);
    }
    __syncthreads();
    float iv = s_inv;
    float4 gv = ((const float4*)g)[t];
    float o[4] = {v.x*iv*gv.x, v.y*iv*gv.y, v.z*iv*gv.z, v.w*iv*gv.w};
    __nv_bfloat16 h[4], l[4];
    #pragma unroll
    for (int i = 0; i < 4; i++) split_bf16(o[i], h[i], l[i]);
    size_t base = (size_t)r * D_MODEL + t*4;
    *(__nv_bfloat162*)(Yh + base)     = __nv_bfloat162(h[0], h[1]);
    *(__nv_bfloat162*)(Yh + base + 2) = __nv_bfloat162(h[2], h[3]);
    *(__nv_bfloat162*)(Yl + base)     = __nv_bfloat162(l[0], l[1]);
    *(__nv_bfloat162*)(Yl + base + 2) = __nv_bfloat162(l[2], l[3]);
}

// -------- ams: out = rmsnorm(A, g) * U -> bf16 hi/lo ------------------------
__global__ void __launch_bounds__(256)
ams_tc(const float* __restrict__ A, const float* __restrict__ g,
       const float* __restrict__ U,
       __nv_bfloat16* __restrict__ Yh, __nv_bfloat16* __restrict__ Yl)
{
    int r = blockIdx.x, t = threadIdx.x;
    float4 v = ((const float4*)(A + (size_t)r * D_MODEL))[t];
    float ss = v.x*v.x + v.y*v.y + v.z*v.z + v.w*v.w;
    #pragma unroll
    for (int o = 16; o; o >>= 1) ss += __shfl_xor_sync(0xffffffffu, ss, o);
    __shared__ float ws[8]; __shared__ float s_inv;
    if ((t & 31) == 0) ws[t >> 5] = ss;
    __syncthreads();
    if (t == 0) {
        float tot = 0.f;
        #pragma unroll
        for (int i = 0; i < 8; i++) tot += ws[i];
        s_inv = rsqrtf(tot * (1.0f / D_MODEL) + 1e-8f);
    }
    __syncthreads();
    float iv = s_inv;
    float4 gv = ((const float4*)g)[t];
    float4 uv = ((const float4*)(U + (size_t)r * D_MODEL))[t];
    float o[4] = {v.x*iv*gv.x*uv.x, v.y*iv*gv.y*uv.y, v.z*iv*gv.z*uv.z, v.w*iv*gv.w*uv.w};
    __nv_bfloat16 h[4], l[4];
    #pragma unroll
    for (int i = 0; i < 4; i++) split_bf16(o[i], h[i], l[i]);
    size_t base = (size_t)r * D_MODEL + t*4;
    *(__nv_bfloat162*)(Yh + base)     = __nv_bfloat162(h[0], h[1]);
    *(__nv_bfloat162*)(Yh + base + 2) = __nv_bfloat162(h[2], h[3]);
    *(__nv_bfloat162*)(Yl + base)     = __nv_bfloat162(l[0], l[1]);
    *(__nv_bfloat162*)(Yl + base + 2) = __nv_bfloat162(l[2], l[3]);
}

// ============== HMMA GEMM (EPI 2 only): C = A@B^T + bias + R ================
#define SM_A_HI 0
#define SM_A_LO 16384
#define SM_B_HI 32768
#define SM_B_LO 65536
#define STAGE_B 98304

__global__ void __launch_bounds__(512, 1)
gemm_res(const __nv_bfloat16* __restrict__ Ah, const __nv_bfloat16* __restrict__ Al,
         const __nv_bfloat16* __restrict__ Bh, const __nv_bfloat16* __restrict__ Bl,
         const float* __restrict__ bias, const float* __restrict__ R,
         float* __restrict__ C, int M, int N, int K)
{
    extern __shared__ __align__(128) char sm[];
    uint32_t sb = smem_u32(sm);
    int tid  = threadIdx.x;
    int wid  = tid >> 5;
    int lane = tid & 31;
    int wm = wid & 1, wn = wid >> 1;
    int bm = blockIdx.y * 128, bn = blockIdx.x * 256;
    int m0 = wm * 64, n0 = wn * 32;

    int laneRow = lane & 15;
    int laneK   = (lane >> 4) * 16;
    uint32_t xorA = (uint32_t)((laneRow & 7) << 4);

    float acc[4][4][4];
    #pragma unroll
    for (int i = 0; i < 4; i++)
        #pragma unroll
        for (int j = 0; j < 4; j++)
            #pragma unroll
            for (int q = 0; q < 4; q++) acc[i][j][q] = 0.f;

    const int NCH = K >> 6;

    auto load_stage = [&](int s, int chunk) {
        uint32_t st = sb + s * STAGE_B;
        int k0 = chunk * 64;
        #pragma unroll
        for (int it = 0; it < 2; it++) {
            int idx = tid + it * 512;
            int row = idx >> 3, c = idx & 7;
            uint32_t d = st + row * 128 + (uint32_t)((c * 16) ^ ((row & 7) << 4));
            size_t go = (size_t)(bm + row) * K + k0 + c * 8;
            cp16(d + SM_A_HI, Ah + go);
            cp16(d + SM_A_LO, Al + go);
        }
        #pragma unroll
        for (int it = 0; it < 4; it++) {
            int idx = tid + it * 512;
            int row = idx >> 3, c = idx & 7;
            uint32_t d = st + row * 128 + (uint32_t)((c * 16) ^ ((row & 7) << 4));
            size_t go = (size_t)(bn + row) * K + k0 + c * 8;
            cp16(d + SM_B_HI, Bh + go);
            cp16(d + SM_B_LO, Bl + go);
        }
    };

    load_stage(0, 0);
    cp_commit();

    for (int chunk = 0; chunk < NCH; chunk++) {
        int s = chunk & 1;
        if (chunk + 1 < NCH) {
            load_stage(s ^ 1, chunk + 1);
            cp_commit();
            cp_wait1();
        } else {
            cp_wait0();
        }
        __syncthreads();

        uint32_t st = sb + s * STAGE_B;
        #pragma unroll
        for (int ks = 0; ks < 4; ks++) {
            uint32_t kb = (uint32_t)((ks * 32 + laneK) ^ xorA);
            uint32_t ah[4][4], bh[2][4];
            #pragma unroll
            for (int i = 0; i < 4; i++)
                ldsm_x4(ah[i], st + SM_A_HI + (uint32_t)(m0 + i*16 + laneRow) * 128 + kb);
            #pragma unroll
            for (int p = 0; p < 2; p++)
                ldsm_x4(bh[p], st + SM_B_HI + (uint32_t)(n0 + p*16 + laneRow) * 128 + kb);
            #pragma unroll
            for (int i = 0; i < 4; i++)
                #pragma unroll
                for (int j = 0; j < 4; j++)
                    mma16816(acc[i][j], ah[i], bh[j>>1][j&1], bh[j>>1][2 + (j&1)]);
            {
                uint32_t al[4][4];
                #pragma unroll
                for (int i = 0; i < 4; i++)
                    ldsm_x4(al[i], st + SM_A_LO + (uint32_t)(m0 + i*16 + laneRow) * 128 + kb);
                #pragma unroll
                for (int i = 0; i < 4; i++)
                    #pragma unroll
                    for (int j = 0; j < 4; j++)
                        mma16816(acc[i][j], al[i], bh[j>>1][j&1], bh[j>>1][2 + (j&1)]);
            }
            {
                uint32_t bl[2][4];
                #pragma unroll
                for (int p = 0; p < 2; p++)
                    ldsm_x4(bl[p], st + SM_B_LO + (uint32_t)(n0 + p*16 + laneRow) * 128 + kb);
                #pragma unroll
                for (int i = 0; i < 4; i++)
                    #pragma unroll
                    for (int j = 0; j < 4; j++)
                        mma16816(acc[i][j], ah[i], bl[j>>1][j&1], bl[j>>1][2 + (j&1)]);
            }
        }
        __syncthreads();
    }

    int group = lane >> 2, tq = lane & 3;
    #pragma unroll
    for (int j = 0; j < 4; j++) {
        int n = bn + n0 + j*8 + tq*2;
        float bv0 = bias[n], bv1 = bias[n+1];
        #pragma unroll
        for (int i = 0; i < 4; i++) {
            int m = bm + m0 + i*16 + group;
            size_t off0 = (size_t)m * N + n;
            size_t off1 = (size_t)(m + 8) * N + n;
            float2 r0 = *(const float2*)(R + off0);
            float2 r1 = *(const float2*)(R + off1);
            *(float2*)(C + off0) = make_float2(acc[i][j][0] + bv0 + r0.x, acc[i][j][1] + bv1 + r0.y);
            *(float2*)(C + off1) = make_float2(acc[i][j][2] + bv0 + r1.x, acc[i][j][3] + bv1 + r1.y);
        }
    }
}

// ====== fused Q/K/V/U projection: one launch, grid.z selects weight ========
__global__ void __launch_bounds__(512, 1)
proj4(const __nv_bfloat16* __restrict__ Ah, const __nv_bfloat16* __restrict__ Al,
      const __nv_bfloat16* __restrict__ WThG, const __nv_bfloat16* __restrict__ WTlG,
      const float* __restrict__ bq, const float* __restrict__ bk,
      const float* __restrict__ bv, const float* __restrict__ bu,
      __nv_bfloat16* __restrict__ Qh, __nv_bfloat16* __restrict__ Ql,
      __nv_bfloat16* __restrict__ Kh, __nv_bfloat16* __restrict__ Kl,
      __nv_bfloat16* __restrict__ VTh, __nv_bfloat16* __restrict__ VTl,
      float* __restrict__ Uf)
{
    extern __shared__ __align__(128) char sm[];
    uint32_t sb = smem_u32(sm);
    int tid  = threadIdx.x;
    int wid  = tid >> 5;
    int lane = tid & 31;
    int wm = wid & 1, wn = wid >> 1;
    int z  = blockIdx.z;
    int bm = blockIdx.y * 128, bn = blockIdx.x * 256;
    int m0 = wm * 64, n0 = wn * 32;
    const int K = 1024, N = 1024;

    const __nv_bfloat16* Bh = WThG + (size_t)z * W1M;
    const __nv_bfloat16* Bl = WTlG + (size_t)z * W1M;
    const float* bias = (z == 0) ? bq : (z == 1) ? bk : (z == 2) ? bv : bu;

    int laneRow = lane & 15;
    int laneK   = (lane >> 4) * 16;
    uint32_t xorA = (uint32_t)((laneRow & 7) << 4);

    float acc[4][4][4];
    #pragma unroll
    for (int i = 0; i < 4; i++)
        #pragma unroll
        for (int j = 0; j < 4; j++)
            #pragma unroll
            for (int q = 0; q < 4; q++) acc[i][j][q] = 0.f;

    const int NCH = K >> 6;

    auto load_stage = [&](int s, int chunk) {
        uint32_t st = sb + s * STAGE_B;
        int k0 = chunk * 64;
        #pragma unroll
        for (int it = 0; it < 2; it++) {
            int idx = tid + it * 512;
            int row = idx >> 3, c = idx & 7;
            uint32_t d = st + row * 128 + (uint32_t)((c * 16) ^ ((row & 7) << 4));
            size_t go = (size_t)(bm + row) * K + k0 + c * 8;
            cp16(d + SM_A_HI, Ah + go);
            cp16(d + SM_A_LO, Al + go);
        }
        #pragma unroll
        for (int it = 0; it < 4; it++) {
            int idx = tid + it * 512;
            int row = idx >> 3, c = idx & 7;
            uint32_t d = st + row * 128 + (uint32_t)((c * 16) ^ ((row & 7) << 4));
            size_t go = (size_t)(bn + row) * K + k0 + c * 8;
            cp16(d + SM_B_HI, Bh + go);
            cp16(d + SM_B_LO, Bl + go);
        }
    };

    load_stage(0, 0);
    cp_commit();

    for (int chunk = 0; chunk < NCH; chunk++) {
        int s = chunk & 1;
        if (chunk + 1 < NCH) {
            load_stage(s ^ 1, chunk + 1);
            cp_commit();
            cp_wait1();
        } else {
            cp_wait0();
        }
        __syncthreads();

        uint32_t st = sb + s * STAGE_B;
        #pragma unroll
        for (int ks = 0; ks < 4; ks++) {
            uint32_t kb = (uint32_t)((ks * 32 + laneK) ^ xorA);
            uint32_t ah[4][4], bh[2][4];
            #pragma unroll
            for (int i = 0; i < 4; i++)
                ldsm_x4(ah[i], st + SM_A_HI + (uint32_t)(m0 + i*16 + laneRow) * 128 + kb);
            #pragma unroll
            for (int p = 0; p < 2; p++)
                ldsm_x4(bh[p], st + SM_B_HI + (uint32_t)(n0 + p*16 + laneRow) * 128 + kb);
            #pragma unroll
            for (int i = 0; i < 4; i++)
                #pragma unroll
                for (int j = 0; j < 4; j++)
                    mma16816(acc[i][j], ah[i], bh[j>>1][j&1], bh[j>>1][2 + (j&1)]);
            {
                uint32_t al[4][4];
                #pragma unroll
                for (int i = 0; i < 4; i++)
                    ldsm_x4(al[i], st + SM_A_LO + (uint32_t)(m0 + i*16 + laneRow) * 128 + kb);
                #pragma unroll
                for (int i = 0; i < 4; i++)
                    #pragma unroll
                    for (int j = 0; j < 4; j++)
                        mma16816(acc[i][j], al[i], bh[j>>1][j&1], bh[j>>1][2 + (j&1)]);
            }
            {
                uint32_t bl[2][4];
                #pragma unroll
                for (int p = 0; p < 2; p++)
                    ldsm_x4(bl[p], st + SM_B_LO + (uint32_t)(n0 + p*16 + laneRow) * 128 + kb);
                #pragma unroll
                for (int i = 0; i < 4; i++)
                    #pragma unroll
                    for (int j = 0; j < 4; j++)
                        mma16816(acc[i][j], ah[i], bl[j>>1][j&1], bl[j>>1][2 + (j&1)]);
            }
        }
        __syncthreads();
    }

    int group = lane >> 2, tq = lane & 3;
    __nv_bfloat16* Yh = (z == 0) ? Qh : Kh;
    __nv_bfloat16* Yl = (z == 0) ? Ql : Kl;
    #pragma unroll
    for (int j = 0; j < 4; j++) {
        int n = bn + n0 + j*8 + tq*2;
        float bv0 = bias[n], bv1 = bias[n+1];
        #pragma unroll
        for (int i = 0; i < 4; i++) {
            int m = bm + m0 + i*16 + group;
            float v0 = acc[i][j][0] + bv0, v1 = acc[i][j][1] + bv1;
            float v2 = acc[i][j][2] + bv0, v3 = acc[i][j][3] + bv1;
            if (z <= 1) {
                __nv_bfloat16 h0,l0,h1,l1,h2,l2,h3,l3;
                split_bf16(v0,h0,l0); split_bf16(v1,h1,l1);
                split_bf16(v2,h2,l2); split_bf16(v3,h3,l3);
                size_t off0 = (size_t)m * N + n;
                size_t off1 = (size_t)(m + 8) * N + n;
                *(__nv_bfloat162*)(Yh + off0) = __nv_bfloat162(h0, h1);
                *(__nv_bfloat162*)(Yl + off0) = __nv_bfloat162(l0, l1);
                *(__nv_bfloat162*)(Yh + off1) = __nv_bfloat162(h2, h3);
                *(__nv_bfloat162*)(Yl + off1) = __nv_bfloat162(l2, l3);
            } else if (z == 2) {
                __nv_bfloat16 h0,l0,h1,l1,h2,l2,h3,l3;
                split_bf16(v0,h0,l0); split_bf16(v1,h1,l1);
                split_bf16(v2,h2,l2); split_bf16(v3,h3,l3);
                int bi = m >> 11, tt = m & 2047;
                int hh = n >> 6,  dd = n & 63;
                size_t vb = ((size_t)((bi*16 + hh)*64 + dd)) * 2048 + tt;
                VTh[vb]        = h0;  VTl[vb]        = l0;
                VTh[vb + 2048] = h1;  VTl[vb + 2048] = l1;
                VTh[vb + 8]    = h2;  VTl[vb + 8]    = l2;
                VTh[vb + 2056] = h3;  VTl[vb + 2056] = l3;
            } else {
                size_t off0 = (size_t)m * N + n;
                size_t off1 = (size_t)(m + 8) * N + n;
                *(float2*)(Uf + off0) = make_float2(siluf(v0), siluf(v1));
                *(float2*)(Uf + off1) = make_float2(siluf(v2), siluf(v3));
            }
        }
    }
}

// ====== w1 GEMM + swiglu fusion ============================================
#define W_A_HI  0
#define W_A_LO  16384
#define W_B1_HI 32768
#define W_B1_LO 49152
#define W_B2_HI 65536
#define W_B2_LO 81920
#define STAGE_W 98304

__global__ void __launch_bounds__(512, 1)
gemm_w1sg(const __nv_bfloat16* __restrict__ Ah, const __nv_bfloat16* __restrict__ Al,
          const __nv_bfloat16* __restrict__ Bh, const __nv_bfloat16* __restrict__ Bl,
          const float* __restrict__ b1,
          __nv_bfloat16* __restrict__ Yh, __nv_bfloat16* __restrict__ Yl)
{
    extern __shared__ __align__(128) char sm[];
    uint32_t sb = smem_u32(sm);
    int tid  = threadIdx.x;
    int wid  = tid >> 5;
    int lane = tid & 31;
    int wm = wid & 1, wn = wid >> 1;
    int bm = blockIdx.y * 128, bn = blockIdx.x * 128;
    int m0 = wm * 64, n0 = wn * 16;
    const int K = 1024;

    int laneRow = lane & 15;
    int laneK   = (lane >> 4) * 16;
    uint32_t xorA = (uint32_t)((laneRow & 7) << 4);

    float acc1[4][2][4], acc2[4][2][4];
    #pragma unroll
    for (int i = 0; i < 4; i++)
        #pragma unroll
        for (int j = 0; j < 2; j++)
            #pragma unroll
            for (int q = 0; q < 4; q++) { acc1[i][j][q] = 0.f; acc2[i][j][q] = 0.f; }

    const int NCH = K >> 6;

    auto load_stage = [&](int s, int chunk) {
        uint32_t st = sb + s * STAGE_W;
        int k0 = chunk * 64;
        #pragma unroll
        for (int it = 0; it < 2; it++) {
            int idx = tid + it * 512;
            int row = idx >> 3, c = idx & 7;
            uint32_t d = st + row * 128 + (uint32_t)((c * 16) ^ ((row & 7) << 4));
            size_t goA  = (size_t)(bm + row) * K + k0 + c * 8;
            size_t goB1 = (size_t)(bn + row) * K + k0 + c * 8;
            size_t goB2 = (size_t)(1024 + bn + row) * K + k0 + c * 8;
            cp16(d + W_A_HI,  Ah + goA);
            cp16(d + W_A_LO,  Al + goA);
            cp16(d + W_B1_HI, Bh + goB1);
            cp16(d + W_B1_LO, Bl + goB1);
            cp16(d + W_B2_HI, Bh + goB2);
            cp16(d + W_B2_LO, Bl + goB2);
        }
    };

    load_stage(0, 0);
    cp_commit();

    for (int chunk = 0; chunk < NCH; chunk++) {
        int s = chunk & 1;
        if (chunk + 1 < NCH) {
            load_stage(s ^ 1, chunk + 1);
            cp_commit();
            cp_wait1();
        } else {
            cp_wait0();
        }
        __syncthreads();

        uint32_t st = sb + s * STAGE_W;
        #pragma unroll
        for (int ks = 0; ks < 4; ks++) {
            uint32_t kb = (uint32_t)((ks * 32 + laneK) ^ xorA);
            uint32_t ah[4][4], b1h[4], b2h[4];
            #pragma unroll
            for (int i = 0; i < 4; i++)
                ldsm_x4(ah[i], st + W_A_HI + (uint32_t)(m0 + i*16 + laneRow) * 128 + kb);
            ldsm_x4(b1h, st + W_B1_HI + (uint32_t)(n0 + laneRow) * 128 + kb);
            ldsm_x4(b2h, st + W_B2_HI + (uint32_t)(n0 + laneRow) * 128 + kb);
            #pragma unroll
            for (int i = 0; i < 4; i++)
                #pragma unroll
                for (int j = 0; j < 2; j++) {
                    mma16816(acc1[i][j], ah[i], b1h[j], b1h[2 + j]);
                    mma16816(acc2[i][j], ah[i], b2h[j], b2h[2 + j]);
                }
            {
                uint32_t al[4][4];
                #pragma unroll
                for (int i = 0; i < 4; i++)
                    ldsm_x4(al[i], st + W_A_LO + (uint32_t)(m0 + i*16 + laneRow) * 128 + kb);
                #pragma unroll
                for (int i = 0; i < 4; i++)
                    #pragma unroll
                    for (int j = 0; j < 2; j++) {
                        mma16816(acc1[i][j], al[i], b1h[j], b1h[2 + j]);
                        mma16816(acc2[i][j], al[i], b2h[j], b2h[2 + j]);
                    }
            }
            {
                uint32_t b1l[4], b2l[4];
                ldsm_x4(b1l, st + W_B1_LO + (uint32_t)(n0 + laneRow) * 128 + kb);
                ldsm_x4(b2l, st + W_B2_LO + (uint32_t)(n0 + laneRow) * 128 + kb);
                #pragma unroll
                for (int i = 0; i < 4; i++)
                    #pragma unroll
                    for (int j = 0; j < 2; j++) {
                        mma16816(acc1[i][j], ah[i], b1l[j], b1l[2 + j]);
                        mma16816(acc2[i][j], ah[i], b2l[j], b2l[2 + j]);
                    }
            }
        }
        __syncthreads();
    }

    int group = lane >> 2, tq = lane & 3;
    #pragma unroll
    for (int j = 0; j < 2; j++) {
        int n = bn + n0 + j*8 + tq*2;
        float c10 = b1[n], c11 = b1[n+1];
        float c20 = b1[1024 + n], c21 = b1[1025 + n];
        #pragma unroll
        for (int i = 0; i < 4; i++) {
            int m = bm + m0 + i*16 + group;
            float y0 = siluf(acc1[i][j][0] + c10) * (acc2[i][j][0] + c20);
            float y1 = siluf(acc1[i][j][1] + c11) * (acc2[i][j][1] + c21);
            float y2 = siluf(acc1[i][j][2] + c10) * (acc2[i][j][2] + c20);
            float y3 = siluf(acc1[i][j][3] + c11) * (acc2[i][j][3] + c21);
            __nv_bfloat16 h0,l0,h1,l1,h2,l2,h3,l3;
            split_bf16(y0,h0,l0); split_bf16(y1,h1,l1);
            split_bf16(y2,h2,l2); split_bf16(y3,h3,l3);
            size_t off0 = (size_t)m * 1024 + n;
            size_t off1 = (size_t)(m + 8) * 1024 + n;
            *(__nv_bfloat162*)(Yh + off0) = __nv_bfloat162(h0, h1);
            *(__nv_bfloat162*)(Yl + off0) = __nv_bfloat162(l0, l1);
            *(__nv_bfloat162*)(Yh + off1) = __nv_bfloat162(h2, h3);
            *(__nv_bfloat162*)(Yl + off1) = __nv_bfloat162(l2, l3);
        }
    }
}

// ===== tensor-core fused SiLU-attention, register-resident S (FA2 layout) ===
// 8 warps split q-tile by m: warp w owns rows [w*16, w*16+16), all 128 keys.
// S C-frags convert in-register to S@V A-frags. No S smem round trip.
#define A_SQH 0u
#define A_SQL 16384u
#define A_SK  32768u       // + s*32768 : KH, KL(+16384)
#define A_SVT 98304u       // + s*32768 : VTH, VTL(+16384)
#define A_PB  163840u      // + s*512
#define ATT_SMEM 164864

__global__ void __launch_bounds__(256, 1)
attn_tc(const __nv_bfloat16* __restrict__ Qh, const __nv_bfloat16* __restrict__ Ql,
        const __nv_bfloat16* __restrict__ Kh, const __nv_bfloat16* __restrict__ Kl,
        const __nv_bfloat16* __restrict__ VTh, const __nv_bfloat16* __restrict__ VTl,
        const float* __restrict__ PB, float* __restrict__ O)
{
    extern __shared__ __align__(128) char sm[];
    uint32_t sb = smem_u32(sm);
    int tid  = threadIdx.x;
    int wid  = tid >> 5;
    int lane = tid & 31;
    int qt = blockIdx.x, h = blockIdx.y, b = blockIdx.z;
    int m0 = wid * 16;

    int laneRow = lane & 15;
    int laneK   = (lane >> 4) * 16;
    uint32_t xorA = (uint32_t)((laneRow & 7) << 4);
    int group = lane >> 2, tq = lane & 3;

    auto load_q = [&]() {
        #pragma unroll
        for (int it = 0; it < 4; it++) {
            int idx = tid + it * 256;
            int row = idx >> 3, c = idx & 7;
            uint32_t d = row * 128 + (uint32_t)((c * 16) ^ ((row & 7) << 4));
            size_t go = ((size_t)(b*SEQ + qt*128 + row)) * D_MODEL + h*64 + c*8;
            cp16(sb + A_SQH + d, Qh + go);
            cp16(sb + A_SQL + d, Ql + go);
        }
    };
    auto load_kv = [&](int s, int kt) {
        uint32_t kbase = sb + A_SK + (uint32_t)s * 32768u;
        #pragma unroll
        for (int it = 0; it < 4; it++) {
            int idx = tid + it * 256;
            int row = idx >> 3, c = idx & 7;
            uint32_t d = row * 128 + (uint32_t)((c * 16) ^ ((row & 7) << 4));
            size_t go = ((size_t)(b*SEQ + kt*128 + row)) * D_MODEL + h*64 + c*8;
            cp16(kbase + d, Kh + go);
            cp16(kbase + 16384u + d, Kl + go);
        }
        uint32_t vbase = sb + A_SVT + (uint32_t)s * 32768u;
        #pragma unroll
        for (int it = 0; it < 4; it++) {
            int idx = tid + it * 256;
            int row = idx >> 4, c = idx & 15;
            uint32_t d = row * 256 + (uint32_t)((c * 16) ^ ((row & 7) << 4));
            size_t go = ((size_t)((b*16 + h)*64 + row)) * 2048 + kt*128 + c*8;
            cp16(vbase + d, VTh + go);
            cp16(vbase + 16384u + d, VTl + go);
        }
        // p_bias gather (plain LDG/STS; visible after next __syncthreads)
        if (tid < 128) {
            float v = PB[(size_t)(kt*128 + tid) * N_HEADS + h];
            *(float*)(sm + A_PB + (uint32_t)s * 512u + tid * 4) = v;
        }
    };

    float accO[8][4];
    #pragma unroll
    for (int f = 0; f < 8; f++)
        #pragma unroll
        for (int q = 0; q < 4; q++) accO[f][q] = 0.f;

    load_q(); cp_commit();
    load_kv(0, 0); cp_commit();
    cp_wait1();          // Q complete
    __syncthreads();

    // hoist Q fragments (loop-invariant)
    uint32_t qfh[4][4], qfl[4][4];
    #pragma unroll
    for (int ks = 0; ks < 4; ks++) {
        uint32_t kb = (uint32_t)((ks * 32 + laneK) ^ xorA);
        ldsm_x4(qfh[ks], sb + A_SQH + (uint32_t)(m0 + laneRow) * 128 + kb);
        ldsm_x4(qfl[ks], sb + A_SQL + (uint32_t)(m0 + laneRow) * 128 + kb);
    }

    for (int kt = 0; kt < SEQ/128; kt++) {
        int s = kt & 1;
        if (kt + 1 < SEQ/128) {
            load_kv(s ^ 1, kt + 1);
            cp_commit();
            cp_wait1();
        } else {
            cp_wait0();
        }
        __syncthreads();

        // ---- S = Q @ K^T : 16 C-frags (8 key-tiles x 2 n8 halves) ----
        float sc[16][4];
        #pragma unroll
        for (int f = 0; f < 16; f++)
            #pragma unroll
            for (int q = 0; q < 4; q++) sc[f][q] = 0.f;

        uint32_t kst = sb + A_SK + (uint32_t)s * 32768u;
        #pragma unroll
        for (int nt = 0; nt < 8; nt++) {
            #pragma unroll
            for (int ks = 0; ks < 4; ks++) {
                uint32_t kb = (uint32_t)((ks * 32 + laneK) ^ xorA);
                uint32_t kh[4];
                ldsm_x4(kh, kst + (uint32_t)(nt*16 + laneRow) * 128 + kb);
                mma16816(sc[2*nt],   qfh[ks], kh[0], kh[2]);
                mma16816(sc[2*nt+1], qfh[ks], kh[1], kh[3]);
                mma16816(sc[2*nt],   qfl[ks], kh[0], kh[2]);
                mma16816(sc[2*nt+1], qfl[ks], kh[1], kh[3]);
                uint32_t kl[4];
                ldsm_x4(kl, kst + 16384u + (uint32_t)(nt*16 + laneRow) * 128 + kb);
                mma16816(sc[2*nt],   qfh[ks], kl[0], kl[2]);
                mma16816(sc[2*nt+1], qfh[ks], kl[1], kl[3]);
            }
        }

        // ---- silu(scale*S + pb), split hi/lo, repack as A-frags in regs ----
        uint32_t sfh[8][4], sfl[8][4];
        const float* pbs = (const float*)(sm + A_PB + (uint32_t)s * 512u);
        #pragma unroll
        for (int nt = 0; nt < 8; nt++) {
            #pragma unroll
            for (int half = 0; half < 2; half++) {
                int f = 2*nt + half;
                int tcol = nt*16 + half*8 + tq*2;
                float pb0 = pbs[tcol], pb1 = pbs[tcol + 1];
                float w0 = siluf(sc[f][0] * 0.125f + pb0);
                float w1 = siluf(sc[f][1] * 0.125f + pb1);
                float w2 = siluf(sc[f][2] * 0.125f + pb0);
                float w3 = siluf(sc[f][3] * 0.125f + pb1);
                __nv_bfloat16 h0,l0,h1,l1,h2,l2,h3,l3;
                split_bf16(w0,h0,l0); split_bf16(w1,h1,l1);
                split_bf16(w2,h2,l2); split_bf16(w3,h3,l3);
                sfh[nt][half*2]     = pack_bf16(h0, h1);   // a0 / a2
                sfh[nt][half*2 + 1] = pack_bf16(h2, h3);   // a1 / a3
                sfl[nt][half*2]     = pack_bf16(l0, l1);
                sfl[nt][half*2 + 1] = pack_bf16(l2, l3);
            }
        }

        // ---- O += S @ V (A in registers, B = VT from smem) ----
        uint32_t vst = sb + A_SVT + (uint32_t)s * 32768u;
        #pragma unroll
        for (int ks = 0; ks < 8; ks++) {
            #pragma unroll
            for (int dn = 0; dn < 4; dn++) {
                uint32_t kb = (uint32_t)((ks * 32 + laneK) ^ xorA);
                uint32_t vh[4];
                ldsm_x4(vh, vst + (uint32_t)(dn*16 + laneRow) * 256 + kb);
                mma16816(accO[2*dn],   sfh[ks], vh[0], vh[2]);
                mma16816(accO[2*dn+1], sfh[ks], vh[1], vh[3]);
                mma16816(accO[2*dn],   sfl[ks], vh[0], vh[2]);
                mma16816(accO[2*dn+1], sfl[ks], vh[1], vh[3]);
                uint32_t vl[4];
                ldsm_x4(vl, vst + 16384u + (uint32_t)(dn*16 + laneRow) * 256 + kb);
                mma16816(accO[2*dn],   sfh[ks], vl[0], vl[2]);
                mma16816(accO[2*dn+1], sfh[ks], vl[1], vl[3]);
            }
        }
        __syncthreads();
    }

    // ---- write O ----
    #pragma unroll
    for (int dn = 0; dn < 4; dn++) {
        #pragma unroll
        for (int half = 0; half < 2; half++) {
            int f = 2*dn + half;
            int col = h*64 + dn*16 + half*8 + tq*2;
            int row = b*SEQ + qt*128 + m0 + group;
            *(float2*)(O + (size_t)row * D_MODEL + col) =
                make_float2(accO[f][0], accO[f][1]);
            *(float2*)(O + (size_t)(row + 8) * D_MODEL + col) =
                make_float2(accO[f][2], accO[f][3]);
        }
    }
}

// ---------------- launch ----------------------------------------------------
extern "C" void kernel_launch(void* const* d_in, const int* in_sizes, int n_in,
                              void* d_out, int out_size)
{
    const float* x      = (const float*)d_in[0];
    const float* pb     = (const float*)d_in[2];
    const float* wq     = (const float*)d_in[3];
    const float* bq     = (const float*)d_in[4];
    const float* wk     = (const float*)d_in[5];
    const float* bk_    = (const float*)d_in[6];
    const float* wv     = (const float*)d_in[7];
    const float* bv     = (const float*)d_in[8];
    const float* wu     = (const float*)d_in[9];
    const float* bu     = (const float*)d_in[10];
    const float* g_ams  = (const float*)d_in[11];
    const float* w0     = (const float*)d_in[12];
    const float* b0     = (const float*)d_in[13];
    const float* w1     = (const float*)d_in[14];
    const float* b1     = (const float*)d_in[15];
    const float* w2     = (const float*)d_in[16];
    const float* b2     = (const float*)d_in[17];
    const float* g_mffn = (const float*)d_in[18];
    float* out = (float*)d_out;

    float *Qf, *Kf, *Vf, *Uf, *AOf, *Of;
    __nv_bfloat16 *A1h, *A1l, *A2h, *A2l, *WTh, *WTl;
    cudaGetSymbolAddress((void**)&Qf,  g_Q);
    cudaGetSymbolAddress((void**)&Kf,  g_K);
    cudaGetSymbolAddress((void**)&Vf,  g_V);
    cudaGetSymbolAddress((void**)&Uf,  g_U);
    cudaGetSymbolAddress((void**)&AOf, g_AO);
    cudaGetSymbolAddress((void**)&Of,  g_O);
    cudaGetSymbolAddress((void**)&A1h, g_A1h);
    cudaGetSymbolAddress((void**)&A1l, g_A1l);
    cudaGetSymbolAddress((void**)&A2h, g_A2h);
    cudaGetSymbolAddress((void**)&A2l, g_A2l);
    cudaGetSymbolAddress((void**)&WTh, g_WTh);
    cudaGetSymbolAddress((void**)&WTl, g_WTl);

    const size_t NEL = (size_t)M_ROWS * D_MODEL;
    __nv_bfloat16 *Qhb = (__nv_bfloat16*)Qf,  *Qlb = Qhb + NEL;
    __nv_bfloat16 *Khb = (__nv_bfloat16*)Kf,  *Klb = Khb + NEL;
    __nv_bfloat16 *VTh = (__nv_bfloat16*)Vf,  *VTl = VTh + NEL;

    __nv_bfloat16 *T0_h = WTh + (size_t)4*W1M, *T0_l = WTl + (size_t)4*W1M;
    __nv_bfloat16 *T2_h = WTh + (size_t)5*W1M, *T2_l = WTl + (size_t)5*W1M;
    __nv_bfloat16 *T1_h = WTh + (size_t)6*W1M, *T1_l = WTl + (size_t)6*W1M;

    const int GSM = 2 * STAGE_B;
    cudaFuncSetAttribute(gemm_res,  cudaFuncAttributeMaxDynamicSharedMemorySize, GSM);
    cudaFuncSetAttribute(proj4,     cudaFuncAttributeMaxDynamicSharedMemorySize, GSM);
    cudaFuncSetAttribute(gemm_w1sg, cudaFuncAttributeMaxDynamicSharedMemorySize, 2*STAGE_W);
    cudaFuncSetAttribute(attn_tc,   cudaFuncAttributeMaxDynamicSharedMemorySize, ATT_SMEM);

    wtsplit_all<<<8192, dim3(32, 8)>>>(wq, wk, wv, wu, w0, w2, w1, WTh, WTl);
    rmsnorm_tc<<<M_ROWS, 256>>>(x, g_ams, A1h, A1l);
    proj4<<<dim3(4, 32, 4), 512, GSM>>>(A1h, A1l, WTh, WTl, bq, bk_, bv, bu,
                                        Qhb, Qlb, Khb, Klb, VTh, VTl, Uf);
    attn_tc<<<dim3(SEQ/128, N_HEADS, BATCH), 256, ATT_SMEM>>>(Qhb, Qlb, Khb, Klb, VTh, VTl, pb, AOf);
    ams_tc<<<M_ROWS, 256>>>(AOf, g_ams, Uf, A2h, A2l);
    gemm_res<<<dim3(4, 32), 512, GSM>>>(A2h, A2l, T0_h, T0_l, b0, x, Of, M_ROWS, 1024, 1024);
    rmsnorm_tc<<<M_ROWS, 256>>>(Of, g_mffn, A1h, A1l);
    gemm_w1sg<<<dim3(8, 32), 512, 2*STAGE_W>>>(A1h, A1l, T1_h, T1_l, b1, A2h, A2l);
    gemm_res<<<dim3(4, 32), 512, GSM>>>(A2h, A2l, T2_h, T2_l, b2, Of, out, M_ROWS, 1024, 1024);
}